// round 1
// baseline (speedup 1.0000x reference)
#include <cuda_runtime.h>
#include <cuda_bf16.h>
#include <cstdio>

#define NN   50000
#define EE   800000
#define RR   8
#define HH   128
#define NEG  0.2f
#define CHUNK 512
#define NB    98      // ceil(50000/512)

// ---------------- scratch (device globals; no runtime allocation) -------------
__device__ float g_xW[RR * NN * HH];       // [R,N,H] per-relation transforms (204.8 MB)
__device__ float g_h [NN * HH];            // layer activations (reused)
__device__ float g_sq[RR * NN];            // xW . q
__device__ float g_sk[RR * NN];            // xW . k
__device__ int   g_rowptr[NN + 1];
__device__ int   g_cursor[NN];             // doubles as degree buffer
__device__ int   g_edges [EE];             // packed: src | (etype<<16)
__device__ int   g_bsums [128];
__device__ int   g_boffs [128];
__device__ float g_Wt[HH * HH];            // Wl transposed

// ---------------- CSR build ---------------------------------------------------
__global__ void k_zero_deg() {
    int i = blockIdx.x * blockDim.x + threadIdx.x;
    if (i < NN) g_cursor[i] = 0;
}

__global__ void k_hist(const int* __restrict__ tgt) {
    int e = blockIdx.x * blockDim.x + threadIdx.x;
    if (e < EE) atomicAdd(&g_cursor[tgt[e]], 1);
}

__global__ void k_scan1() {
    __shared__ int sm[CHUNK];
    int b = blockIdx.x, t = threadIdx.x;
    int i = b * CHUNK + t;
    int v = (i < NN) ? g_cursor[i] : 0;
    sm[t] = v;
    __syncthreads();
    for (int off = 1; off < CHUNK; off <<= 1) {
        int x = (t >= off) ? sm[t - off] : 0;
        __syncthreads();
        sm[t] += x;
        __syncthreads();
    }
    if (i < NN) g_rowptr[i] = sm[t] - v;   // block-local exclusive
    if (t == CHUNK - 1) g_bsums[b] = sm[t];
}

__global__ void k_scan2() {
    __shared__ int sm[128];
    int t = threadIdx.x;
    int v = (t < NB) ? g_bsums[t] : 0;
    sm[t] = v;
    __syncthreads();
    for (int off = 1; off < 128; off <<= 1) {
        int x = (t >= off) ? sm[t - off] : 0;
        __syncthreads();
        sm[t] += x;
        __syncthreads();
    }
    g_boffs[t] = sm[t] - v;
}

__global__ void k_scan3() {
    int i = blockIdx.x * blockDim.x + threadIdx.x;
    if (i < NN) {
        int rp = g_rowptr[i] + g_boffs[i / CHUNK];
        g_rowptr[i] = rp;
        g_cursor[i] = rp;
    }
    if (i == 0) g_rowptr[NN] = EE;
}

__global__ void k_fill(const int* __restrict__ src, const int* __restrict__ tgt,
                       const int* __restrict__ etype) {
    int e = blockIdx.x * blockDim.x + threadIdx.x;
    if (e < EE) {
        int t = tgt[e];
        int pos = atomicAdd(&g_cursor[t], 1);
        g_edges[pos] = src[e] | (etype[e] << 16);
    }
}

__global__ void k_trans(const float* __restrict__ Wl) {
    int idx = blockIdx.x * blockDim.x + threadIdx.x;
    if (idx < HH * HH) {
        int j = idx / HH, k = idx % HH;
        g_Wt[k * HH + j] = Wl[idx];
    }
}

// ---------------- GEMM: Y[r] = X @ W[r]  (+ fused sq/sk epilogue) -------------
// BM=64, BN=128(full), BK=16, 256 threads, thread tile 8x4.
template <bool EPI, bool FINAL>
__global__ void __launch_bounds__(256)
k_gemm(const float* __restrict__ X, const float* __restrict__ Wall,
       float* __restrict__ Y,
       float* __restrict__ sq, float* __restrict__ sk,
       const float* __restrict__ qv, const float* __restrict__ kv,
       const float* __restrict__ bias)
{
    __shared__ __align__(16) float As[16][64];
    __shared__ __align__(16) float Bs[16][128];

    const int r    = blockIdx.y;
    const int row0 = blockIdx.x * 64;
    const float* W = Wall + (size_t)r * HH * HH;

    const int tid = threadIdx.x;
    const int rg  = tid >> 5;    // warp -> 8 rows
    const int cg  = tid & 31;    // lane -> 4 cols

    float C[8][4];
#pragma unroll
    for (int i = 0; i < 8; i++)
#pragma unroll
        for (int j = 0; j < 4; j++) C[i][j] = 0.f;

    const int mA  = tid & 63;
    const int kbA = (tid >> 6) << 2;

    for (int k0 = 0; k0 < 128; k0 += 16) {
        // A tile 64x16 (transposed into As[k][m])
        int row = row0 + mA;
        float4 av = make_float4(0.f, 0.f, 0.f, 0.f);
        if (row < NN) av = *(const float4*)&X[(size_t)row * 128 + k0 + kbA];
        As[kbA + 0][mA] = av.x;
        As[kbA + 1][mA] = av.y;
        As[kbA + 2][mA] = av.z;
        As[kbA + 3][mA] = av.w;
        // B tile 16x128 (contiguous)
        const float4* Wp = (const float4*)&W[k0 * 128];
        ((float4*)Bs)[tid]       = Wp[tid];
        ((float4*)Bs)[tid + 256] = Wp[tid + 256];
        __syncthreads();

#pragma unroll
        for (int kk = 0; kk < 16; kk++) {
            float4 b4 = *(const float4*)&Bs[kk][cg * 4];
            float4 a0 = *(const float4*)&As[kk][rg * 8];
            float4 a1 = *(const float4*)&As[kk][rg * 8 + 4];
            float a[8] = {a0.x, a0.y, a0.z, a0.w, a1.x, a1.y, a1.z, a1.w};
#pragma unroll
            for (int i = 0; i < 8; i++) {
                C[i][0] += a[i] * b4.x;
                C[i][1] += a[i] * b4.y;
                C[i][2] += a[i] * b4.z;
                C[i][3] += a[i] * b4.w;
            }
        }
        __syncthreads();
    }

    float4 bv = make_float4(0.f, 0.f, 0.f, 0.f);
    float4 q4 = make_float4(0.f, 0.f, 0.f, 0.f);
    float4 kk4 = make_float4(0.f, 0.f, 0.f, 0.f);
    if (FINAL) bv = *(const float4*)&bias[cg * 4];
    if (EPI) {
        q4  = *(const float4*)&qv[cg * 4];
        kk4 = *(const float4*)&kv[cg * 4];
    }

#pragma unroll
    for (int i = 0; i < 8; i++) {
        int row = row0 + rg * 8 + i;       // warp-uniform
        if (row < NN) {
            float4 o = make_float4(C[i][0], C[i][1], C[i][2], C[i][3]);
            if (FINAL) { o.x += bv.x; o.y += bv.y; o.z += bv.z; o.w += bv.w; }
            *(float4*)&Y[((size_t)r * NN + row) * HH + cg * 4] = o;
            if (EPI) {
                float pq = o.x * q4.x + o.y * q4.y + o.z * q4.z + o.w * q4.w;
                float pk = o.x * kk4.x + o.y * kk4.y + o.z * kk4.z + o.w * kk4.w;
#pragma unroll
                for (int off = 16; off; off >>= 1) {
                    pq += __shfl_down_sync(0xffffffffu, pq, off);
                    pk += __shfl_down_sync(0xffffffffu, pk, off);
                }
                if (cg == 0) {
                    sq[r * NN + row] = pq;
                    sk[r * NN + row] = pk;
                }
            }
        }
    }
}

// ---------------- attention softmax + aggregation (warp per node) -------------
__global__ void __launch_bounds__(256)
k_agg(const float* __restrict__ xW, const float* __restrict__ sq,
      const float* __restrict__ sk, const float* __restrict__ bias,
      float* __restrict__ out)
{
    int warp = (blockIdx.x * blockDim.x + threadIdx.x) >> 5;
    int lane = threadIdx.x & 31;
    if (warp >= NN) return;
    const int n     = warp;
    const int start = g_rowptr[n];
    const int end   = g_rowptr[n + 1];

    // pass 1: segment max of leaky-relu alpha
    float m = -1e30f;
    for (int j0 = start; j0 < end; j0 += 32) {
        int j = j0 + lane;
        float a = -1e30f;
        if (j < end) {
            int p = g_edges[j];
            int s = p & 0xffff, et = p >> 16;
            float v = sq[et * NN + n] + sk[et * NN + s];
            a = v > 0.f ? v : NEG * v;
        }
        m = fmaxf(m, a);
    }
#pragma unroll
    for (int off = 16; off; off >>= 1)
        m = fmaxf(m, __shfl_xor_sync(0xffffffffu, m, off));

    // pass 2: exp-weights + weighted gather of xW[etype, src] rows
    float4 acc = make_float4(0.f, 0.f, 0.f, 0.f);
    float den = 0.f;
    for (int j0 = start; j0 < end; j0 += 32) {
        int j = j0 + lane;
        float w = 0.f; int s = 0, et = 0;
        if (j < end) {
            int p = g_edges[j];
            s = p & 0xffff; et = p >> 16;
            float v = sq[et * NN + n] + sk[et * NN + s];
            v = v > 0.f ? v : NEG * v;
            w = __expf(v - m);
        }
        den += w;
        int cnt = min(32, end - j0);
        for (int t = 0; t < cnt; t++) {
            float wt = __shfl_sync(0xffffffffu, w, t);
            int   st = __shfl_sync(0xffffffffu, s, t);
            int   rt = __shfl_sync(0xffffffffu, et, t);
            float4 v4 = *(const float4*)&xW[((size_t)rt * NN + st) * HH + lane * 4];
            acc.x += wt * v4.x;
            acc.y += wt * v4.y;
            acc.z += wt * v4.z;
            acc.w += wt * v4.w;
        }
    }
#pragma unroll
    for (int off = 16; off; off >>= 1)
        den += __shfl_xor_sync(0xffffffffu, den, off);

    float inv = 1.f / (den + 1e-16f);
    float4 bv = *(const float4*)&bias[lane * 4];
    float4 o;
    o.x = fmaxf(acc.x * inv + bv.x, 0.f);
    o.y = fmaxf(acc.y * inv + bv.y, 0.f);
    o.z = fmaxf(acc.z * inv + bv.z, 0.f);
    o.w = fmaxf(acc.w * inv + bv.w, 0.f);
    *(float4*)&out[(size_t)n * HH + lane * 4] = o;
}

// ---------------- launch ------------------------------------------------------
extern "C" void kernel_launch(void* const* d_in, const int* in_sizes, int n_in,
                              void* d_out, int out_size)
{
    const float* x  = (const float*)d_in[0];
    const int*   ei = (const int*)  d_in[1];
    const int*   et = (const int*)  d_in[2];
    const float* W1 = (const float*)d_in[4];
    const float* q1 = (const float*)d_in[5];
    const float* k1 = (const float*)d_in[6];
    const float* b1 = (const float*)d_in[7];
    const float* W2 = (const float*)d_in[8];
    const float* q2 = (const float*)d_in[9];
    const float* k2 = (const float*)d_in[10];
    const float* b2 = (const float*)d_in[11];
    const float* Wl = (const float*)d_in[12];
    const float* bl = (const float*)d_in[13];
    float* out = (float*)d_out;

    const int* srcp = ei;
    const int* tgtp = ei + EE;

    float *pxW, *ph, *psq, *psk, *pWt;
    cudaGetSymbolAddress((void**)&pxW, g_xW);
    cudaGetSymbolAddress((void**)&ph,  g_h);
    cudaGetSymbolAddress((void**)&psq, g_sq);
    cudaGetSymbolAddress((void**)&psk, g_sk);
    cudaGetSymbolAddress((void**)&pWt, g_Wt);

    // CSR build (shared by both layers)
    k_zero_deg<<<(NN + 255) / 256, 256>>>();
    k_hist<<<(EE + 255) / 256, 256>>>(tgtp);
    k_scan1<<<NB, CHUNK>>>();
    k_scan2<<<1, 128>>>();
    k_scan3<<<(NN + 255) / 256, 256>>>();
    k_fill<<<(EE + 255) / 256, 256>>>(srcp, tgtp, et);
    k_trans<<<(HH * HH + 255) / 256, 256>>>(Wl);

    const int GT = (NN + 63) / 64;           // 782 row tiles
    dim3 gemm_grid(GT, RR);
    const int agg_blocks = (NN * 32 + 255) / 256;

    // Layer 1
    k_gemm<true, false><<<gemm_grid, 256>>>(x,  W1, pxW, psq, psk, q1, k1, nullptr);
    k_agg<<<agg_blocks, 256>>>(pxW, psq, psk, b1, ph);

    // Layer 2
    k_gemm<true, false><<<gemm_grid, 256>>>(ph, W2, pxW, psq, psk, q2, k2, nullptr);
    k_agg<<<agg_blocks, 256>>>(pxW, psq, psk, b2, ph);

    // Final linear (h @ Wl^T + bl) straight into d_out
    k_gemm<false, true><<<dim3(GT, 1), 256>>>(ph, pWt, out, nullptr, nullptr,
                                              nullptr, nullptr, bl);
    (void)in_sizes; (void)n_in; (void)out_size;
}

// round 3
// speedup vs baseline: 1.5448x; 1.5448x over previous
#include <cuda_runtime.h>
#include <cuda_bf16.h>
#include <cstdint>

#define NN   50000
#define EE   800000
#define RR   8
#define HH   128
#define NEG  0.2f
#define CHUNK 512
#define NB    98      // ceil(50000/512)

// ---------------- scratch (device globals; no runtime allocation) -------------
__device__ float g_xW[RR * NN * HH];       // [R,N,H] per-relation transforms
__device__ float g_h [NN * HH];            // layer activations (reused)
__device__ float g_sq[RR * NN];            // xW . q
__device__ float g_sk[RR * NN];            // xW . k
__device__ int   g_rowptr[NN + 1];
__device__ int   g_cursor[NN];
__device__ int   g_edges [EE];             // packed: src | (etype<<16)
__device__ int   g_bsums [128];
__device__ int   g_boffs [128];
__device__ float g_Wt[HH * HH];            // Wl transposed
// bf16 hi/lo weight images, [R][N][K] plain layout (Wt[n][k] = W[k][n])
__device__ __nv_bfloat16 g_B1hi[RR * 16384];
__device__ __nv_bfloat16 g_B1lo[RR * 16384];
__device__ __nv_bfloat16 g_B2hi[RR * 16384];
__device__ __nv_bfloat16 g_B2lo[RR * 16384];

// ---------------- PTX helpers (baseline sm_103: mma.sync + ldmatrix) ----------
__device__ __forceinline__ uint32_t smem_u32(const void* p) {
    uint32_t a;
    asm("{ .reg .u64 t; cvta.to.shared.u64 t, %1; cvt.u32.u64 %0, t; }" : "=r"(a) : "l"(p));
    return a;
}
__device__ __forceinline__ void ldsm4(uint32_t* r, uint32_t addr) {
    asm volatile("ldmatrix.sync.aligned.m8n8.x4.shared.b16 {%0,%1,%2,%3}, [%4];"
                 : "=r"(r[0]), "=r"(r[1]), "=r"(r[2]), "=r"(r[3]) : "r"(addr));
}
__device__ __forceinline__ void mma16816(float* c, const uint32_t* a,
                                         uint32_t b0, uint32_t b1) {
    asm volatile(
        "mma.sync.aligned.m16n8k16.row.col.f32.bf16.bf16.f32 "
        "{%0,%1,%2,%3}, {%4,%5,%6,%7}, {%8,%9}, {%0,%1,%2,%3};"
        : "+f"(c[0]), "+f"(c[1]), "+f"(c[2]), "+f"(c[3])
        : "r"(a[0]), "r"(a[1]), "r"(a[2]), "r"(a[3]), "r"(b0), "r"(b1));
}

// smem tile geometry: 128 rows x 136 bf16 (272 B) -> conflict-free ldmatrix
#define ROWB 272
#define TILEB (128 * ROWB)     // 34816 bytes

// ---------------- CSR build ---------------------------------------------------
__global__ void k_zero_deg() {
    int i = blockIdx.x * blockDim.x + threadIdx.x;
    if (i < NN) g_cursor[i] = 0;
}
__global__ void k_hist(const int* __restrict__ tgt) {
    int e = blockIdx.x * blockDim.x + threadIdx.x;
    if (e < EE) atomicAdd(&g_cursor[tgt[e]], 1);
}
__global__ void k_scan1() {
    __shared__ int sm[CHUNK];
    int b = blockIdx.x, t = threadIdx.x;
    int i = b * CHUNK + t;
    int v = (i < NN) ? g_cursor[i] : 0;
    sm[t] = v;
    __syncthreads();
    for (int off = 1; off < CHUNK; off <<= 1) {
        int x = (t >= off) ? sm[t - off] : 0;
        __syncthreads();
        sm[t] += x;
        __syncthreads();
    }
    if (i < NN) g_rowptr[i] = sm[t] - v;
    if (t == CHUNK - 1) g_bsums[b] = sm[t];
}
__global__ void k_scan2() {
    __shared__ int sm[128];
    int t = threadIdx.x;
    int v = (t < NB) ? g_bsums[t] : 0;
    sm[t] = v;
    __syncthreads();
    for (int off = 1; off < 128; off <<= 1) {
        int x = (t >= off) ? sm[t - off] : 0;
        __syncthreads();
        sm[t] += x;
        __syncthreads();
    }
    g_boffs[t] = sm[t] - v;
}
__global__ void k_scan3() {
    int i = blockIdx.x * blockDim.x + threadIdx.x;
    if (i < NN) {
        int rp = g_rowptr[i] + g_boffs[i / CHUNK];
        g_rowptr[i] = rp;
        g_cursor[i] = rp;
    }
    if (i == 0) g_rowptr[NN] = EE;
}
__global__ void k_fill(const int* __restrict__ src, const int* __restrict__ tgt,
                       const int* __restrict__ etype) {
    int e = blockIdx.x * blockDim.x + threadIdx.x;
    if (e < EE) {
        int t = tgt[e];
        int pos = atomicAdd(&g_cursor[t], 1);
        g_edges[pos] = src[e] | (etype[e] << 16);
    }
}
__global__ void k_trans(const float* __restrict__ Wl) {
    int idx = blockIdx.x * blockDim.x + threadIdx.x;
    if (idx < HH * HH) {
        int j = idx / HH, k = idx % HH;
        g_Wt[k * HH + j] = Wl[idx];
    }
}

// ---------------- weight prep: transpose + bf16 hi/lo split -------------------
__global__ void k_prepB(const float* __restrict__ W,
                        __nv_bfloat16* __restrict__ Bhi,
                        __nv_bfloat16* __restrict__ Blo) {
    int idx = blockIdx.x * blockDim.x + threadIdx.x;   // R*16384
    if (idx >= RR * 16384) return;
    int r = idx >> 14, rem = idx & 16383;
    int n = rem >> 7, k = rem & 127;
    float w = W[r * 16384 + k * 128 + n];              // Wt[n][k] = W[k][n]
    __nv_bfloat16 hi = __float2bfloat16(w);
    __nv_bfloat16 lo = __float2bfloat16(w - __bfloat162float(hi));
    Bhi[r * 16384 + n * 128 + k] = hi;
    Blo[r * 16384 + n * 128 + k] = lo;
}

// ---------------- HMMA GEMM: Y[r] = X @ Wt[r]^T  (+ fused sq/sk) --------------
// grid (391, R); 256 threads = 8 warps (4 m x 2 n); warp tile 32x64.
__global__ void __launch_bounds__(256)
k_gemm_tc(const float* __restrict__ X,
          const __nv_bfloat16* __restrict__ Bhi, const __nv_bfloat16* __restrict__ Blo,
          float* __restrict__ Y, float* __restrict__ sq, float* __restrict__ sk,
          const float* __restrict__ qv, const float* __restrict__ kv)
{
    extern __shared__ char dynsm[];
    char* sAhi = dynsm;
    char* sAlo = dynsm + TILEB;
    char* sBhi = dynsm + 2 * TILEB;
    char* sBlo = dynsm + 3 * TILEB;

    __shared__ float s_q[128], s_k[128];
    __shared__ float s_redq[256], s_redk[256];

    const int tid  = threadIdx.x;
    const int wid  = tid >> 5;
    const int lane = tid & 31;
    const int mw   = wid & 3;          // m offset 32*mw
    const int nw   = wid >> 2;         // n offset 64*nw
    const int r    = blockIdx.y;
    const int row0 = blockIdx.x * 128;

    if (tid < 128) { s_q[tid] = qv[tid]; s_k[tid] = kv[tid]; }

    // --- B copy gmem [N][K] -> smem padded rows (hi and lo) ---
    {
        const uint4* gh = (const uint4*)(Bhi + (size_t)r * 16384);
        const uint4* gl = (const uint4*)(Blo + (size_t)r * 16384);
#pragma unroll
        for (int i = 0; i < 8; i++) {
            int c = tid + 256 * i;             // 2048 16B-chunks
            int row = c >> 4, c16 = c & 15;
            uint32_t off = row * ROWB + c16 * 16;
            *(uint4*)(sBhi + off) = gh[c];
            *(uint4*)(sBlo + off) = gl[c];
        }
    }
    // --- A convert: fp32 -> bf16 hi/lo into padded rows ---
#pragma unroll
    for (int i = 0; i < 8; i++) {
        int c   = tid + 256 * i;               // 2048 chunks of 8 floats
        int row = c >> 4;
        int kc  = (c & 15) << 3;
        int grow = row0 + row;
        float v[8];
        if (grow < NN) {
            const float4* p = (const float4*)&X[(size_t)grow * 128 + kc];
            float4 f0 = p[0], f1 = p[1];
            v[0]=f0.x; v[1]=f0.y; v[2]=f0.z; v[3]=f0.w;
            v[4]=f1.x; v[5]=f1.y; v[6]=f1.z; v[7]=f1.w;
        } else {
#pragma unroll
            for (int j = 0; j < 8; j++) v[j] = 0.f;
        }
        uint32_t hp[4], lp[4];
#pragma unroll
        for (int j = 0; j < 4; j++) {
            __nv_bfloat16 h0 = __float2bfloat16(v[2*j]);
            __nv_bfloat16 h1 = __float2bfloat16(v[2*j+1]);
            __nv_bfloat16 l0 = __float2bfloat16(v[2*j]   - __bfloat162float(h0));
            __nv_bfloat16 l1 = __float2bfloat16(v[2*j+1] - __bfloat162float(h1));
            hp[j] = (uint32_t)__bfloat16_as_ushort(h0) | ((uint32_t)__bfloat16_as_ushort(h1) << 16);
            lp[j] = (uint32_t)__bfloat16_as_ushort(l0) | ((uint32_t)__bfloat16_as_ushort(l1) << 16);
        }
        uint32_t off = row * ROWB + kc * 2;
        *(uint4*)(sAhi + off) = make_uint4(hp[0], hp[1], hp[2], hp[3]);
        *(uint4*)(sAlo + off) = make_uint4(lp[0], lp[1], lp[2], lp[3]);
    }
    __syncthreads();

    // --- mainloop: c += Ahi*Bhi + Ahi*Blo + Alo*Bhi ---
    float acc[2][8][4];
#pragma unroll
    for (int mt = 0; mt < 2; mt++)
#pragma unroll
        for (int nt = 0; nt < 8; nt++)
#pragma unroll
            for (int j = 0; j < 4; j++) acc[mt][nt][j] = 0.f;

    // ldmatrix lane addresses
    const uint32_t aHiB = smem_u32(sAhi), aLoB = smem_u32(sAlo);
    const uint32_t bHiB = smem_u32(sBhi), bLoB = smem_u32(sBlo);
    // A: lanes 0-7 rows m..m+7 @k, 8-15 rows m+8.. @k, 16-23 rows m.. @k+8, 24-31 m+8.. @k+8
    const int arow  = mw * 32 + (lane & 7) + ((lane >> 3) & 1) * 8;
    const int akcol = (lane >> 4) * 8;
    const uint32_t aoff = (uint32_t)(arow * ROWB + akcol * 2);
    // B: lanes 0-7 n..n+7 @k, 8-15 n..n+7 @k+8, 16-23 n+8..15 @k, 24-31 n+8..15 @k+8
    const int brow  = nw * 64 + (lane & 7) + ((lane >> 4) & 1) * 8;
    const int bkcol = ((lane >> 3) & 1) * 8;
    const uint32_t boff = (uint32_t)(brow * ROWB + bkcol * 2);

#pragma unroll
    for (int ks = 0; ks < 8; ks++) {
        const uint32_t ko = ks * 32;           // 16 cols * 2B
        uint32_t ah[2][4], al[2][4], bh[4][4], bl[4][4];
        ldsm4(ah[0], aHiB + aoff + ko);
        ldsm4(ah[1], aHiB + aoff + 16 * ROWB + ko);
        ldsm4(al[0], aLoB + aoff + ko);
        ldsm4(al[1], aLoB + aoff + 16 * ROWB + ko);
#pragma unroll
        for (int p = 0; p < 4; p++) {
            ldsm4(bh[p], bHiB + boff + p * 16 * ROWB + ko);
            ldsm4(bl[p], bLoB + boff + p * 16 * ROWB + ko);
        }
#pragma unroll
        for (int mt = 0; mt < 2; mt++)
#pragma unroll
            for (int p = 0; p < 4; p++) {
                mma16816(acc[mt][2*p],   ah[mt], bh[p][0], bh[p][1]);
                mma16816(acc[mt][2*p],   ah[mt], bl[p][0], bl[p][1]);
                mma16816(acc[mt][2*p],   al[mt], bh[p][0], bh[p][1]);
                mma16816(acc[mt][2*p+1], ah[mt], bh[p][2], bh[p][3]);
                mma16816(acc[mt][2*p+1], ah[mt], bl[p][2], bl[p][3]);
                mma16816(acc[mt][2*p+1], al[mt], bh[p][2], bh[p][3]);
            }
    }

    // --- epilogue: store Y + fused sq/sk ---
    // fragment (mt,nt) reg j: row = mw*32+mt*16+lane/4 (+8 for j>=2), col = nw*64+nt*8+(lane%4)*2 (+1 for odd j)
    float pq[4] = {0.f, 0.f, 0.f, 0.f};   // [mt*2 + half]
    float pk[4] = {0.f, 0.f, 0.f, 0.f};
#pragma unroll
    for (int mt = 0; mt < 2; mt++) {
        const int lrow = mw * 32 + mt * 16 + (lane >> 2);
        const int grow = row0 + lrow;
#pragma unroll
        for (int nt = 0; nt < 8; nt++) {
            const int col = nw * 64 + nt * 8 + (lane & 3) * 2;
            float c0 = acc[mt][nt][0], c1 = acc[mt][nt][1];
            float c2 = acc[mt][nt][2], c3 = acc[mt][nt][3];
            float q0 = s_q[col], q1 = s_q[col + 1];
            float k0 = s_k[col], k1 = s_k[col + 1];
            pq[mt*2]   += c0 * q0 + c1 * q1;
            pq[mt*2+1] += c2 * q0 + c3 * q1;
            pk[mt*2]   += c0 * k0 + c1 * k1;
            pk[mt*2+1] += c2 * k0 + c3 * k1;
            if (grow < NN)
                *(float2*)&Y[((size_t)r * NN + grow) * HH + col] = make_float2(c0, c1);
            if (grow + 8 < NN)
                *(float2*)&Y[((size_t)r * NN + grow + 8) * HH + col] = make_float2(c2, c3);
        }
    }
#pragma unroll
    for (int off = 1; off <= 2; off <<= 1)
#pragma unroll
        for (int j = 0; j < 4; j++) {
            pq[j] += __shfl_xor_sync(0xffffffffu, pq[j], off);
            pk[j] += __shfl_xor_sync(0xffffffffu, pk[j], off);
        }
    if ((lane & 3) == 0) {
#pragma unroll
        for (int mt = 0; mt < 2; mt++) {
            int lrow = mw * 32 + mt * 16 + (lane >> 2);
            s_redq[nw * 128 + lrow]     = pq[mt*2];
            s_redq[nw * 128 + lrow + 8] = pq[mt*2+1];
            s_redk[nw * 128 + lrow]     = pk[mt*2];
            s_redk[nw * 128 + lrow + 8] = pk[mt*2+1];
        }
    }
    __syncthreads();
    if (tid < 128) {
        int grow = row0 + tid;
        if (grow < NN) {
            sq[r * NN + grow] = s_redq[tid] + s_redq[128 + tid];
            sk[r * NN + grow] = s_redk[tid] + s_redk[128 + tid];
        }
    }
}

// ---------------- FFMA GEMM for the final 128x128 linear ----------------------
__global__ void __launch_bounds__(256)
k_gemm_final(const float* __restrict__ X, const float* __restrict__ W,
             float* __restrict__ Y, const float* __restrict__ bias)
{
    __shared__ __align__(16) float As[16][64];
    __shared__ __align__(16) float Bs[16][128];
    const int row0 = blockIdx.x * 64;
    const int tid = threadIdx.x;
    const int rg  = tid >> 5;
    const int cg  = tid & 31;

    float C[8][4];
#pragma unroll
    for (int i = 0; i < 8; i++)
#pragma unroll
        for (int j = 0; j < 4; j++) C[i][j] = 0.f;

    const int mA  = tid & 63;
    const int kbA = (tid >> 6) << 2;

    for (int k0 = 0; k0 < 128; k0 += 16) {
        int row = row0 + mA;
        float4 av = make_float4(0.f, 0.f, 0.f, 0.f);
        if (row < NN) av = *(const float4*)&X[(size_t)row * 128 + k0 + kbA];
        As[kbA + 0][mA] = av.x;
        As[kbA + 1][mA] = av.y;
        As[kbA + 2][mA] = av.z;
        As[kbA + 3][mA] = av.w;
        const float4* Wp = (const float4*)&W[k0 * 128];
        ((float4*)Bs)[tid]       = Wp[tid];
        ((float4*)Bs)[tid + 256] = Wp[tid + 256];
        __syncthreads();
#pragma unroll
        for (int kk = 0; kk < 16; kk++) {
            float4 b4 = *(const float4*)&Bs[kk][cg * 4];
            float4 a0 = *(const float4*)&As[kk][rg * 8];
            float4 a1 = *(const float4*)&As[kk][rg * 8 + 4];
            float a[8] = {a0.x, a0.y, a0.z, a0.w, a1.x, a1.y, a1.z, a1.w};
#pragma unroll
            for (int i = 0; i < 8; i++) {
                C[i][0] += a[i] * b4.x;
                C[i][1] += a[i] * b4.y;
                C[i][2] += a[i] * b4.z;
                C[i][3] += a[i] * b4.w;
            }
        }
        __syncthreads();
    }
    float4 bv = *(const float4*)&bias[cg * 4];
#pragma unroll
    for (int i = 0; i < 8; i++) {
        int row = row0 + rg * 8 + i;
        if (row < NN) {
            float4 o = make_float4(C[i][0] + bv.x, C[i][1] + bv.y,
                                   C[i][2] + bv.z, C[i][3] + bv.w);
            *(float4*)&Y[(size_t)row * HH + cg * 4] = o;
        }
    }
}

// ---------------- attention softmax + aggregation (warp per node) -------------
__global__ void __launch_bounds__(256)
k_agg(const float* __restrict__ xW, const float* __restrict__ sq,
      const float* __restrict__ sk, const float* __restrict__ bias,
      float* __restrict__ out)
{
    int warp = (blockIdx.x * blockDim.x + threadIdx.x) >> 5;
    int lane = threadIdx.x & 31;
    if (warp >= NN) return;
    const int n     = warp;
    const int start = g_rowptr[n];
    const int end   = g_rowptr[n + 1];

    float m = -1e30f;
    for (int j0 = start; j0 < end; j0 += 32) {
        int j = j0 + lane;
        float a = -1e30f;
        if (j < end) {
            int p = g_edges[j];
            int s = p & 0xffff, et = p >> 16;
            float v = sq[et * NN + n] + sk[et * NN + s];
            a = v > 0.f ? v : NEG * v;
        }
        m = fmaxf(m, a);
    }
#pragma unroll
    for (int off = 16; off; off >>= 1)
        m = fmaxf(m, __shfl_xor_sync(0xffffffffu, m, off));

    float4 acc = make_float4(0.f, 0.f, 0.f, 0.f);
    float den = 0.f;
    for (int j0 = start; j0 < end; j0 += 32) {
        int j = j0 + lane;
        float w = 0.f; int s = 0, et = 0;
        if (j < end) {
            int p = g_edges[j];
            s = p & 0xffff; et = p >> 16;
            float v = sq[et * NN + n] + sk[et * NN + s];
            v = v > 0.f ? v : NEG * v;
            w = __expf(v - m);
        }
        den += w;
        int cnt = min(32, end - j0);
        for (int t = 0; t < cnt; t++) {
            float wt = __shfl_sync(0xffffffffu, w, t);
            int   st = __shfl_sync(0xffffffffu, s, t);
            int   rt = __shfl_sync(0xffffffffu, et, t);
            float4 v4 = *(const float4*)&xW[((size_t)rt * NN + st) * HH + lane * 4];
            acc.x += wt * v4.x;
            acc.y += wt * v4.y;
            acc.z += wt * v4.z;
            acc.w += wt * v4.w;
        }
    }
#pragma unroll
    for (int off = 16; off; off >>= 1)
        den += __shfl_xor_sync(0xffffffffu, den, off);

    float inv = 1.f / (den + 1e-16f);
    float4 bv = *(const float4*)&bias[lane * 4];
    float4 o;
    o.x = fmaxf(acc.x * inv + bv.x, 0.f);
    o.y = fmaxf(acc.y * inv + bv.y, 0.f);
    o.z = fmaxf(acc.z * inv + bv.z, 0.f);
    o.w = fmaxf(acc.w * inv + bv.w, 0.f);
    *(float4*)&out[(size_t)n * HH + lane * 4] = o;
}

// ---------------- launch ------------------------------------------------------
extern "C" void kernel_launch(void* const* d_in, const int* in_sizes, int n_in,
                              void* d_out, int out_size)
{
    const float* x  = (const float*)d_in[0];
    const int*   ei = (const int*)  d_in[1];
    const int*   et = (const int*)  d_in[2];
    const float* W1 = (const float*)d_in[4];
    const float* q1 = (const float*)d_in[5];
    const float* k1 = (const float*)d_in[6];
    const float* b1 = (const float*)d_in[7];
    const float* W2 = (const float*)d_in[8];
    const float* q2 = (const float*)d_in[9];
    const float* k2 = (const float*)d_in[10];
    const float* b2 = (const float*)d_in[11];
    const float* Wl = (const float*)d_in[12];
    const float* bl = (const float*)d_in[13];
    float* out = (float*)d_out;

    const int* srcp = ei;
    const int* tgtp = ei + EE;

    float *pxW, *ph, *psq, *psk, *pWt;
    __nv_bfloat16 *pB1h, *pB1l, *pB2h, *pB2l;
    cudaGetSymbolAddress((void**)&pxW, g_xW);
    cudaGetSymbolAddress((void**)&ph,  g_h);
    cudaGetSymbolAddress((void**)&psq, g_sq);
    cudaGetSymbolAddress((void**)&psk, g_sk);
    cudaGetSymbolAddress((void**)&pWt, g_Wt);
    cudaGetSymbolAddress((void**)&pB1h, g_B1hi);
    cudaGetSymbolAddress((void**)&pB1l, g_B1lo);
    cudaGetSymbolAddress((void**)&pB2h, g_B2hi);
    cudaGetSymbolAddress((void**)&pB2l, g_B2lo);

    const int SMEM_TC = 4 * TILEB;   // 139264
    static int attr_set = 0;
    cudaFuncSetAttribute(k_gemm_tc, cudaFuncAttributeMaxDynamicSharedMemorySize, SMEM_TC);
    (void)attr_set;

    // CSR build + weight prep
    k_zero_deg<<<(NN + 255) / 256, 256>>>();
    k_hist<<<(EE + 255) / 256, 256>>>(tgtp);
    k_scan1<<<NB, CHUNK>>>();
    k_scan2<<<1, 128>>>();
    k_scan3<<<(NN + 255) / 256, 256>>>();
    k_fill<<<(EE + 255) / 256, 256>>>(srcp, tgtp, et);
    k_trans<<<(HH * HH + 255) / 256, 256>>>(Wl);
    k_prepB<<<(RR * 16384 + 255) / 256, 256>>>(W1, pB1h, pB1l);
    k_prepB<<<(RR * 16384 + 255) / 256, 256>>>(W2, pB2h, pB2l);

    const int GT128 = (NN + 127) / 128;      // 391 row tiles
    dim3 tc_grid(GT128, RR);
    const int agg_blocks = (NN * 32 + 255) / 256;

    // Layer 1
    k_gemm_tc<<<tc_grid, 256, SMEM_TC>>>(x,  pB1h, pB1l, pxW, psq, psk, q1, k1);
    k_agg<<<agg_blocks, 256>>>(pxW, psq, psk, b1, ph);

    // Layer 2
    k_gemm_tc<<<tc_grid, 256, SMEM_TC>>>(ph, pB2h, pB2l, pxW, psq, psk, q2, k2);
    k_agg<<<agg_blocks, 256>>>(pxW, psq, psk, b2, ph);

    // Final linear (h @ Wl^T + bl) straight into d_out
    k_gemm_final<<<(NN + 63) / 64, 256>>>(ph, pWt, out, bl);
    (void)in_sizes; (void)n_in; (void)out_size;
}

// round 4
// speedup vs baseline: 1.6868x; 1.0919x over previous
#include <cuda_runtime.h>
#include <cuda_bf16.h>
#include <cuda_fp16.h>
#include <cstdint>

#define NN   50000
#define EE   800000
#define RR   8
#define HH   128
#define NEG  0.2f
#define CHUNK 512
#define NB    98      // ceil(50000/512)

// ---------------- scratch (device globals; no runtime allocation) -------------
__device__ __half g_xW16[RR * NN * HH];    // [R,N,H] per-relation transforms (fp16, 102.4 MB)
__device__ float g_h [NN * HH];            // layer activations (fp32)
__device__ float g_sq[RR * NN];            // xW . q (fp32)
__device__ float g_sk[RR * NN];            // xW . k
__device__ int   g_rowptr[NN + 1];
__device__ int   g_cursor[NN];
__device__ int   g_edges [EE];             // packed: src | (etype<<16)
__device__ int   g_bsums [128];
__device__ int   g_boffs [128];
__device__ float g_Wt[HH * HH];            // Wl transposed
// bf16 hi/lo weight images, [R][N][K] plain layout (Wt[n][k] = W[k][n])
__device__ __nv_bfloat16 g_B1hi[RR * 16384];
__device__ __nv_bfloat16 g_B1lo[RR * 16384];
__device__ __nv_bfloat16 g_B2hi[RR * 16384];
__device__ __nv_bfloat16 g_B2lo[RR * 16384];

// ---------------- PTX helpers (baseline sm_103: mma.sync + ldmatrix) ----------
__device__ __forceinline__ uint32_t smem_u32(const void* p) {
    uint32_t a;
    asm("{ .reg .u64 t; cvta.to.shared.u64 t, %1; cvt.u32.u64 %0, t; }" : "=r"(a) : "l"(p));
    return a;
}
__device__ __forceinline__ void ldsm4(uint32_t* r, uint32_t addr) {
    asm volatile("ldmatrix.sync.aligned.m8n8.x4.shared.b16 {%0,%1,%2,%3}, [%4];"
                 : "=r"(r[0]), "=r"(r[1]), "=r"(r[2]), "=r"(r[3]) : "r"(addr));
}
__device__ __forceinline__ void mma16816(float* c, const uint32_t* a,
                                         uint32_t b0, uint32_t b1) {
    asm volatile(
        "mma.sync.aligned.m16n8k16.row.col.f32.bf16.bf16.f32 "
        "{%0,%1,%2,%3}, {%4,%5,%6,%7}, {%8,%9}, {%0,%1,%2,%3};"
        : "+f"(c[0]), "+f"(c[1]), "+f"(c[2]), "+f"(c[3])
        : "r"(a[0]), "r"(a[1]), "r"(a[2]), "r"(a[3]), "r"(b0), "r"(b1));
}

// smem tile geometry: 128 rows x 136 bf16 (272 B) -> conflict-free ldmatrix
#define ROWB 272
#define TILEB (128 * ROWB)     // 34816 bytes

// ---------------- CSR build ---------------------------------------------------
__global__ void k_zero_deg() {
    int i = blockIdx.x * blockDim.x + threadIdx.x;
    if (i < NN) g_cursor[i] = 0;
}
__global__ void k_hist(const int* __restrict__ tgt) {
    int e = blockIdx.x * blockDim.x + threadIdx.x;
    if (e < EE) atomicAdd(&g_cursor[tgt[e]], 1);
}
__global__ void k_scan1() {
    __shared__ int sm[CHUNK];
    int b = blockIdx.x, t = threadIdx.x;
    int i = b * CHUNK + t;
    int v = (i < NN) ? g_cursor[i] : 0;
    sm[t] = v;
    __syncthreads();
    for (int off = 1; off < CHUNK; off <<= 1) {
        int x = (t >= off) ? sm[t - off] : 0;
        __syncthreads();
        sm[t] += x;
        __syncthreads();
    }
    if (i < NN) g_rowptr[i] = sm[t] - v;
    if (t == CHUNK - 1) g_bsums[b] = sm[t];
}
__global__ void k_scan2() {
    __shared__ int sm[128];
    int t = threadIdx.x;
    int v = (t < NB) ? g_bsums[t] : 0;
    sm[t] = v;
    __syncthreads();
    for (int off = 1; off < 128; off <<= 1) {
        int x = (t >= off) ? sm[t - off] : 0;
        __syncthreads();
        sm[t] += x;
        __syncthreads();
    }
    g_boffs[t] = sm[t] - v;
}
__global__ void k_scan3() {
    int i = blockIdx.x * blockDim.x + threadIdx.x;
    if (i < NN) {
        int rp = g_rowptr[i] + g_boffs[i / CHUNK];
        g_rowptr[i] = rp;
        g_cursor[i] = rp;
    }
    if (i == 0) g_rowptr[NN] = EE;
}
__global__ void k_fill(const int* __restrict__ src, const int* __restrict__ tgt,
                       const int* __restrict__ etype) {
    int e = blockIdx.x * blockDim.x + threadIdx.x;
    if (e < EE) {
        int t = tgt[e];
        int pos = atomicAdd(&g_cursor[t], 1);
        g_edges[pos] = src[e] | (etype[e] << 16);
    }
}
__global__ void k_trans(const float* __restrict__ Wl) {
    int idx = blockIdx.x * blockDim.x + threadIdx.x;
    if (idx < HH * HH) {
        int j = idx / HH, k = idx % HH;
        g_Wt[k * HH + j] = Wl[idx];
    }
}

// ---------------- weight prep: transpose + bf16 hi/lo split -------------------
__global__ void k_prepB(const float* __restrict__ W,
                        __nv_bfloat16* __restrict__ Bhi,
                        __nv_bfloat16* __restrict__ Blo) {
    int idx = blockIdx.x * blockDim.x + threadIdx.x;   // R*16384
    if (idx >= RR * 16384) return;
    int r = idx >> 14, rem = idx & 16383;
    int n = rem >> 7, k = rem & 127;
    float w = W[r * 16384 + k * 128 + n];              // Wt[n][k] = W[k][n]
    __nv_bfloat16 hi = __float2bfloat16(w);
    __nv_bfloat16 lo = __float2bfloat16(w - __bfloat162float(hi));
    Bhi[r * 16384 + n * 128 + k] = hi;
    Blo[r * 16384 + n * 128 + k] = lo;
}

// ---------------- HMMA GEMM: Y16[r] = fp16(X @ Wt[r]^T), fused sq/sk ----------
// grid (391, R); 256 threads = 8 warps (4 m x 2 n); warp tile 32x64.
__global__ void __launch_bounds__(256)
k_gemm_tc(const float* __restrict__ X,
          const __nv_bfloat16* __restrict__ Bhi, const __nv_bfloat16* __restrict__ Blo,
          __half* __restrict__ Y, float* __restrict__ sq, float* __restrict__ sk,
          const float* __restrict__ qv, const float* __restrict__ kv)
{
    extern __shared__ char dynsm[];
    char* sAhi = dynsm;
    char* sAlo = dynsm + TILEB;
    char* sBhi = dynsm + 2 * TILEB;
    char* sBlo = dynsm + 3 * TILEB;

    __shared__ float s_q[128], s_k[128];
    __shared__ float s_redq[256], s_redk[256];

    const int tid  = threadIdx.x;
    const int wid  = tid >> 5;
    const int lane = tid & 31;
    const int mw   = wid & 3;          // m offset 32*mw
    const int nw   = wid >> 2;         // n offset 64*nw
    const int r    = blockIdx.y;
    const int row0 = blockIdx.x * 128;

    if (tid < 128) { s_q[tid] = qv[tid]; s_k[tid] = kv[tid]; }

    // --- B copy gmem [N][K] -> smem padded rows (hi and lo) ---
    {
        const uint4* gh = (const uint4*)(Bhi + (size_t)r * 16384);
        const uint4* gl = (const uint4*)(Blo + (size_t)r * 16384);
#pragma unroll
        for (int i = 0; i < 8; i++) {
            int c = tid + 256 * i;             // 2048 16B-chunks
            int row = c >> 4, c16 = c & 15;
            uint32_t off = row * ROWB + c16 * 16;
            *(uint4*)(sBhi + off) = gh[c];
            *(uint4*)(sBlo + off) = gl[c];
        }
    }
    // --- A convert: fp32 -> bf16 hi/lo into padded rows ---
#pragma unroll
    for (int i = 0; i < 8; i++) {
        int c   = tid + 256 * i;               // 2048 chunks of 8 floats
        int row = c >> 4;
        int kc  = (c & 15) << 3;
        int grow = row0 + row;
        float v[8];
        if (grow < NN) {
            const float4* p = (const float4*)&X[(size_t)grow * 128 + kc];
            float4 f0 = p[0], f1 = p[1];
            v[0]=f0.x; v[1]=f0.y; v[2]=f0.z; v[3]=f0.w;
            v[4]=f1.x; v[5]=f1.y; v[6]=f1.z; v[7]=f1.w;
        } else {
#pragma unroll
            for (int j = 0; j < 8; j++) v[j] = 0.f;
        }
        uint32_t hp[4], lp[4];
#pragma unroll
        for (int j = 0; j < 4; j++) {
            __nv_bfloat16 h0 = __float2bfloat16(v[2*j]);
            __nv_bfloat16 h1 = __float2bfloat16(v[2*j+1]);
            __nv_bfloat16 l0 = __float2bfloat16(v[2*j]   - __bfloat162float(h0));
            __nv_bfloat16 l1 = __float2bfloat16(v[2*j+1] - __bfloat162float(h1));
            hp[j] = (uint32_t)__bfloat16_as_ushort(h0) | ((uint32_t)__bfloat16_as_ushort(h1) << 16);
            lp[j] = (uint32_t)__bfloat16_as_ushort(l0) | ((uint32_t)__bfloat16_as_ushort(l1) << 16);
        }
        uint32_t off = row * ROWB + kc * 2;
        *(uint4*)(sAhi + off) = make_uint4(hp[0], hp[1], hp[2], hp[3]);
        *(uint4*)(sAlo + off) = make_uint4(lp[0], lp[1], lp[2], lp[3]);
    }
    __syncthreads();

    // --- mainloop: c += Ahi*Bhi + Ahi*Blo + Alo*Bhi ---
    float acc[2][8][4];
#pragma unroll
    for (int mt = 0; mt < 2; mt++)
#pragma unroll
        for (int nt = 0; nt < 8; nt++)
#pragma unroll
            for (int j = 0; j < 4; j++) acc[mt][nt][j] = 0.f;

    const uint32_t aHiB = smem_u32(sAhi), aLoB = smem_u32(sAlo);
    const uint32_t bHiB = smem_u32(sBhi), bLoB = smem_u32(sBlo);
    const int arow  = mw * 32 + (lane & 7) + ((lane >> 3) & 1) * 8;
    const int akcol = (lane >> 4) * 8;
    const uint32_t aoff = (uint32_t)(arow * ROWB + akcol * 2);
    const int brow  = nw * 64 + (lane & 7) + ((lane >> 4) & 1) * 8;
    const int bkcol = ((lane >> 3) & 1) * 8;
    const uint32_t boff = (uint32_t)(brow * ROWB + bkcol * 2);

#pragma unroll
    for (int ks = 0; ks < 8; ks++) {
        const uint32_t ko = ks * 32;           // 16 cols * 2B
        uint32_t ah[2][4], al[2][4], bh[4][4], bl[4][4];
        ldsm4(ah[0], aHiB + aoff + ko);
        ldsm4(ah[1], aHiB + aoff + 16 * ROWB + ko);
        ldsm4(al[0], aLoB + aoff + ko);
        ldsm4(al[1], aLoB + aoff + 16 * ROWB + ko);
#pragma unroll
        for (int p = 0; p < 4; p++) {
            ldsm4(bh[p], bHiB + boff + p * 16 * ROWB + ko);
            ldsm4(bl[p], bLoB + boff + p * 16 * ROWB + ko);
        }
#pragma unroll
        for (int mt = 0; mt < 2; mt++)
#pragma unroll
            for (int p = 0; p < 4; p++) {
                mma16816(acc[mt][2*p],   ah[mt], bh[p][0], bh[p][1]);
                mma16816(acc[mt][2*p],   ah[mt], bl[p][0], bl[p][1]);
                mma16816(acc[mt][2*p],   al[mt], bh[p][0], bh[p][1]);
                mma16816(acc[mt][2*p+1], ah[mt], bh[p][2], bh[p][3]);
                mma16816(acc[mt][2*p+1], ah[mt], bl[p][2], bl[p][3]);
                mma16816(acc[mt][2*p+1], al[mt], bh[p][2], bh[p][3]);
            }
    }

    // --- epilogue: fp16 store of Y + fused fp32 sq/sk ---
    float pq[4] = {0.f, 0.f, 0.f, 0.f};
    float pk[4] = {0.f, 0.f, 0.f, 0.f};
#pragma unroll
    for (int mt = 0; mt < 2; mt++) {
        const int lrow = mw * 32 + mt * 16 + (lane >> 2);
        const int grow = row0 + lrow;
#pragma unroll
        for (int nt = 0; nt < 8; nt++) {
            const int col = nw * 64 + nt * 8 + (lane & 3) * 2;
            float c0 = acc[mt][nt][0], c1 = acc[mt][nt][1];
            float c2 = acc[mt][nt][2], c3 = acc[mt][nt][3];
            float q0 = s_q[col], q1 = s_q[col + 1];
            float k0 = s_k[col], k1 = s_k[col + 1];
            pq[mt*2]   += c0 * q0 + c1 * q1;
            pq[mt*2+1] += c2 * q0 + c3 * q1;
            pk[mt*2]   += c0 * k0 + c1 * k1;
            pk[mt*2+1] += c2 * k0 + c3 * k1;
            if (grow < NN) {
                __half2 h01 = __floats2half2_rn(c0, c1);
                *(__half2*)&Y[((size_t)r * NN + grow) * HH + col] = h01;
            }
            if (grow + 8 < NN) {
                __half2 h23 = __floats2half2_rn(c2, c3);
                *(__half2*)&Y[((size_t)r * NN + grow + 8) * HH + col] = h23;
            }
        }
    }
#pragma unroll
    for (int off = 1; off <= 2; off <<= 1)
#pragma unroll
        for (int j = 0; j < 4; j++) {
            pq[j] += __shfl_xor_sync(0xffffffffu, pq[j], off);
            pk[j] += __shfl_xor_sync(0xffffffffu, pk[j], off);
        }
    if ((lane & 3) == 0) {
#pragma unroll
        for (int mt = 0; mt < 2; mt++) {
            int lrow = mw * 32 + mt * 16 + (lane >> 2);
            s_redq[nw * 128 + lrow]     = pq[mt*2];
            s_redq[nw * 128 + lrow + 8] = pq[mt*2+1];
            s_redk[nw * 128 + lrow]     = pk[mt*2];
            s_redk[nw * 128 + lrow + 8] = pk[mt*2+1];
        }
    }
    __syncthreads();
    if (tid < 128) {
        int grow = row0 + tid;
        if (grow < NN) {
            sq[r * NN + grow] = s_redq[tid] + s_redq[128 + tid];
            sk[r * NN + grow] = s_redk[tid] + s_redk[128 + tid];
        }
    }
}

// ---------------- FFMA GEMM for the final 128x128 linear ----------------------
__global__ void __launch_bounds__(256)
k_gemm_final(const float* __restrict__ X, const float* __restrict__ W,
             float* __restrict__ Y, const float* __restrict__ bias)
{
    __shared__ __align__(16) float As[16][64];
    __shared__ __align__(16) float Bs[16][128];
    const int row0 = blockIdx.x * 64;
    const int tid = threadIdx.x;
    const int rg  = tid >> 5;
    const int cg  = tid & 31;

    float C[8][4];
#pragma unroll
    for (int i = 0; i < 8; i++)
#pragma unroll
        for (int j = 0; j < 4; j++) C[i][j] = 0.f;

    const int mA  = tid & 63;
    const int kbA = (tid >> 6) << 2;

    for (int k0 = 0; k0 < 128; k0 += 16) {
        int row = row0 + mA;
        float4 av = make_float4(0.f, 0.f, 0.f, 0.f);
        if (row < NN) av = *(const float4*)&X[(size_t)row * 128 + k0 + kbA];
        As[kbA + 0][mA] = av.x;
        As[kbA + 1][mA] = av.y;
        As[kbA + 2][mA] = av.z;
        As[kbA + 3][mA] = av.w;
        const float4* Wp = (const float4*)&W[k0 * 128];
        ((float4*)Bs)[tid]       = Wp[tid];
        ((float4*)Bs)[tid + 256] = Wp[tid + 256];
        __syncthreads();
#pragma unroll
        for (int kk = 0; kk < 16; kk++) {
            float4 b4 = *(const float4*)&Bs[kk][cg * 4];
            float4 a0 = *(const float4*)&As[kk][rg * 8];
            float4 a1 = *(const float4*)&As[kk][rg * 8 + 4];
            float a[8] = {a0.x, a0.y, a0.z, a0.w, a1.x, a1.y, a1.z, a1.w};
#pragma unroll
            for (int i = 0; i < 8; i++) {
                C[i][0] += a[i] * b4.x;
                C[i][1] += a[i] * b4.y;
                C[i][2] += a[i] * b4.z;
                C[i][3] += a[i] * b4.w;
            }
        }
        __syncthreads();
    }
    float4 bv = *(const float4*)&bias[cg * 4];
#pragma unroll
    for (int i = 0; i < 8; i++) {
        int row = row0 + rg * 8 + i;
        if (row < NN) {
            float4 o = make_float4(C[i][0] + bv.x, C[i][1] + bv.y,
                                   C[i][2] + bv.z, C[i][3] + bv.w);
            *(float4*)&Y[(size_t)row * HH + cg * 4] = o;
        }
    }
}

// ---------------- attention softmax + aggregation (warp per node) -------------
__global__ void __launch_bounds__(256)
k_agg(const __half* __restrict__ xW, const float* __restrict__ sq,
      const float* __restrict__ sk, const float* __restrict__ bias,
      float* __restrict__ out)
{
    int warp = (blockIdx.x * blockDim.x + threadIdx.x) >> 5;
    int lane = threadIdx.x & 31;
    if (warp >= NN) return;
    const int n     = warp;
    const int start = g_rowptr[n];
    const int end   = g_rowptr[n + 1];

    float m = -1e30f;
    for (int j0 = start; j0 < end; j0 += 32) {
        int j = j0 + lane;
        float a = -1e30f;
        if (j < end) {
            int p = g_edges[j];
            int s = p & 0xffff, et = p >> 16;
            float v = sq[et * NN + n] + sk[et * NN + s];
            a = v > 0.f ? v : NEG * v;
        }
        m = fmaxf(m, a);
    }
#pragma unroll
    for (int off = 16; off; off >>= 1)
        m = fmaxf(m, __shfl_xor_sync(0xffffffffu, m, off));

    float4 acc = make_float4(0.f, 0.f, 0.f, 0.f);
    float den = 0.f;
    for (int j0 = start; j0 < end; j0 += 32) {
        int j = j0 + lane;
        float w = 0.f; int s = 0, et = 0;
        if (j < end) {
            int p = g_edges[j];
            s = p & 0xffff; et = p >> 16;
            float v = sq[et * NN + n] + sk[et * NN + s];
            v = v > 0.f ? v : NEG * v;
            w = __expf(v - m);
        }
        den += w;
        int cnt = min(32, end - j0);
        for (int t = 0; t < cnt; t++) {
            float wt = __shfl_sync(0xffffffffu, w, t);
            int   st = __shfl_sync(0xffffffffu, s, t);
            int   rt = __shfl_sync(0xffffffffu, et, t);
            // each lane reads 8B (4 halves) of the 256B row
            const uint2 raw = *(const uint2*)&xW[((size_t)rt * NN + st) * HH + lane * 4];
            __half2 h01 = *(const __half2*)&raw.x;
            __half2 h23 = *(const __half2*)&raw.y;
            float2 f01 = __half22float2(h01);
            float2 f23 = __half22float2(h23);
            acc.x += wt * f01.x;
            acc.y += wt * f01.y;
            acc.z += wt * f23.x;
            acc.w += wt * f23.y;
        }
    }
#pragma unroll
    for (int off = 16; off; off >>= 1)
        den += __shfl_xor_sync(0xffffffffu, den, off);

    float inv = 1.f / (den + 1e-16f);
    float4 bv = *(const float4*)&bias[lane * 4];
    float4 o;
    o.x = fmaxf(acc.x * inv + bv.x, 0.f);
    o.y = fmaxf(acc.y * inv + bv.y, 0.f);
    o.z = fmaxf(acc.z * inv + bv.z, 0.f);
    o.w = fmaxf(acc.w * inv + bv.w, 0.f);
    *(float4*)&out[(size_t)n * HH + lane * 4] = o;
}

// ---------------- launch ------------------------------------------------------
extern "C" void kernel_launch(void* const* d_in, const int* in_sizes, int n_in,
                              void* d_out, int out_size)
{
    const float* x  = (const float*)d_in[0];
    const int*   ei = (const int*)  d_in[1];
    const int*   et = (const int*)  d_in[2];
    const float* W1 = (const float*)d_in[4];
    const float* q1 = (const float*)d_in[5];
    const float* k1 = (const float*)d_in[6];
    const float* b1 = (const float*)d_in[7];
    const float* W2 = (const float*)d_in[8];
    const float* q2 = (const float*)d_in[9];
    const float* k2 = (const float*)d_in[10];
    const float* b2 = (const float*)d_in[11];
    const float* Wl = (const float*)d_in[12];
    const float* bl = (const float*)d_in[13];
    float* out = (float*)d_out;

    const int* srcp = ei;
    const int* tgtp = ei + EE;

    float *ph, *psq, *psk, *pWt;
    __half* pxW;
    __nv_bfloat16 *pB1h, *pB1l, *pB2h, *pB2l;
    cudaGetSymbolAddress((void**)&pxW, g_xW16);
    cudaGetSymbolAddress((void**)&ph,  g_h);
    cudaGetSymbolAddress((void**)&psq, g_sq);
    cudaGetSymbolAddress((void**)&psk, g_sk);
    cudaGetSymbolAddress((void**)&pWt, g_Wt);
    cudaGetSymbolAddress((void**)&pB1h, g_B1hi);
    cudaGetSymbolAddress((void**)&pB1l, g_B1lo);
    cudaGetSymbolAddress((void**)&pB2h, g_B2hi);
    cudaGetSymbolAddress((void**)&pB2l, g_B2lo);

    const int SMEM_TC = 4 * TILEB;   // 139264
    cudaFuncSetAttribute(k_gemm_tc, cudaFuncAttributeMaxDynamicSharedMemorySize, SMEM_TC);

    // CSR build + weight prep
    k_zero_deg<<<(NN + 255) / 256, 256>>>();
    k_hist<<<(EE + 255) / 256, 256>>>(tgtp);
    k_scan1<<<NB, CHUNK>>>();
    k_scan2<<<1, 128>>>();
    k_scan3<<<(NN + 255) / 256, 256>>>();
    k_fill<<<(EE + 255) / 256, 256>>>(srcp, tgtp, et);
    k_trans<<<(HH * HH + 255) / 256, 256>>>(Wl);
    k_prepB<<<(RR * 16384 + 255) / 256, 256>>>(W1, pB1h, pB1l);
    k_prepB<<<(RR * 16384 + 255) / 256, 256>>>(W2, pB2h, pB2l);

    const int GT128 = (NN + 127) / 128;      // 391 row tiles
    dim3 tc_grid(GT128, RR);
    const int agg_blocks = (NN * 32 + 255) / 256;

    // Layer 1
    k_gemm_tc<<<tc_grid, 256, SMEM_TC>>>(x,  pB1h, pB1l, pxW, psq, psk, q1, k1);
    k_agg<<<agg_blocks, 256>>>(pxW, psq, psk, b1, ph);

    // Layer 2
    k_gemm_tc<<<tc_grid, 256, SMEM_TC>>>(ph, pB2h, pB2l, pxW, psq, psk, q2, k2);
    k_agg<<<agg_blocks, 256>>>(pxW, psq, psk, b2, ph);

    // Final linear (h @ Wl^T + bl) straight into d_out
    k_gemm_final<<<(NN + 63) / 64, 256>>>(ph, pWt, out, bl);
    (void)in_sizes; (void)n_in; (void)out_size;
}

// round 5
// speedup vs baseline: 1.7263x; 1.0234x over previous
#include <cuda_runtime.h>
#include <cuda_bf16.h>
#include <cuda_fp16.h>
#include <cstdint>

#define NN   50000
#define EE   800000
#define RR   8
#define HH   128
#define NEG  0.2f
#define SCAN_T 1024

// ---------------- scratch (device globals; no runtime allocation) -------------
__device__ __half g_xW16[RR * NN * HH];    // [R,N,H] per-relation transforms (fp16)
__device__ float g_h [NN * HH];            // layer activations (fp32)
__device__ float g_sq[RR * NN];            // xW . q (fp32)
__device__ float g_sk[RR * NN];            // xW . k
__device__ int   g_rowptr[NN + 1];
__device__ int   g_cursor[NN];
__device__ int   g_edges [EE];             // packed: src | (etype<<16)
// bf16 hi/lo weight images, [R][N][K] plain layout
__device__ __nv_bfloat16 g_B1hi[RR * 16384];
__device__ __nv_bfloat16 g_B1lo[RR * 16384];
__device__ __nv_bfloat16 g_B2hi[RR * 16384];
__device__ __nv_bfloat16 g_B2lo[RR * 16384];
__device__ __nv_bfloat16 g_Blhi[16384];    // final linear (Wl, no transpose)
__device__ __nv_bfloat16 g_Bllo[16384];

// ---------------- PTX helpers -------------------------------------------------
__device__ __forceinline__ uint32_t smem_u32(const void* p) {
    uint32_t a;
    asm("{ .reg .u64 t; cvta.to.shared.u64 t, %1; cvt.u32.u64 %0, t; }" : "=r"(a) : "l"(p));
    return a;
}
__device__ __forceinline__ void ldsm4(uint32_t* r, uint32_t addr) {
    asm volatile("ldmatrix.sync.aligned.m8n8.x4.shared.b16 {%0,%1,%2,%3}, [%4];"
                 : "=r"(r[0]), "=r"(r[1]), "=r"(r[2]), "=r"(r[3]) : "r"(addr));
}
__device__ __forceinline__ void mma16816(float* c, const uint32_t* a,
                                         uint32_t b0, uint32_t b1) {
    asm volatile(
        "mma.sync.aligned.m16n8k16.row.col.f32.bf16.bf16.f32 "
        "{%0,%1,%2,%3}, {%4,%5,%6,%7}, {%8,%9}, {%0,%1,%2,%3};"
        : "+f"(c[0]), "+f"(c[1]), "+f"(c[2]), "+f"(c[3])
        : "r"(a[0]), "r"(a[1]), "r"(a[2]), "r"(a[3]), "r"(b0), "r"(b1));
}

// smem geometry
#define ROWB 272                      // padded bf16 row: 136 halves = 272 B
#define ATILE (64 * ROWB)             // 17408
#define BTILE (128 * ROWB)            // 34816
#define SMEM_TC (2 * ATILE + 2 * BTILE)   // 104448
#define F32STRIDE 528                 // fp32 epilogue tile row stride (bytes)

// ---------------- CSR build ---------------------------------------------------
__global__ void k_zero_deg() {
    int i = blockIdx.x * blockDim.x + threadIdx.x;
    if (i < NN) g_cursor[i] = 0;
}
__global__ void k_hist(const int* __restrict__ tgt) {
    int e = blockIdx.x * blockDim.x + threadIdx.x;
    if (e < EE) atomicAdd(&g_cursor[tgt[e]], 1);
}
// one-block scan: degrees (in g_cursor) -> exclusive rowptr + cursor
__global__ void __launch_bounds__(SCAN_T) k_scan_one() {
    __shared__ int part[SCAN_T];
    int t = threadIdx.x;
    const int per = (NN + SCAN_T - 1) / SCAN_T;    // 49
    int lo = t * per;
    int hi = lo + per; if (hi > NN) hi = NN;
    int s = 0;
    for (int i = lo; i < hi; i++) s += g_cursor[i];
    part[t] = s;
    __syncthreads();
    for (int off = 1; off < SCAN_T; off <<= 1) {
        int v = (t >= off) ? part[t - off] : 0;
        __syncthreads();
        part[t] += v;
        __syncthreads();
    }
    int run = (t > 0) ? part[t - 1] : 0;
    for (int i = lo; i < hi; i++) {
        int d = g_cursor[i];
        g_rowptr[i] = run;
        g_cursor[i] = run;
        run += d;
    }
    if (t == 0) g_rowptr[NN] = EE;
}
__global__ void k_fill(const int* __restrict__ src, const int* __restrict__ tgt,
                       const int* __restrict__ etype) {
    int e = blockIdx.x * blockDim.x + threadIdx.x;
    if (e < EE) {
        int t = tgt[e];
        int pos = atomicAdd(&g_cursor[t], 1);
        g_edges[pos] = src[e] | (etype[e] << 16);
    }
}

// ---------------- weight prep: all weights -> bf16 hi/lo images ---------------
__global__ void k_prep(const float* __restrict__ W1, const float* __restrict__ W2,
                       const float* __restrict__ Wl) {
    int idx = blockIdx.x * blockDim.x + threadIdx.x;
    const int RW = RR * 16384;
    if (idx >= 2 * RW + 16384) return;
    float w;
    __nv_bfloat16 *dh, *dl;
    int dsti;
    if (idx < 2 * RW) {
        const float* W = (idx < RW) ? W1 : W2;
        int i = (idx < RW) ? idx : idx - RW;
        int r = i >> 14, rem = i & 16383;
        int n = rem >> 7, k = rem & 127;
        w = W[r * 16384 + k * 128 + n];          // transpose: Wt[n][k] = W[k][n]
        dh = (idx < RW) ? g_B1hi : g_B2hi;
        dl = (idx < RW) ? g_B1lo : g_B2lo;
        dsti = r * 16384 + n * 128 + k;
    } else {
        int i = idx - 2 * RW;                    // Wl: out[i][j] = sum_k h[i][k]*Wl[j][k]
        w = Wl[i];                               // B[j][k] = Wl[j][k], no transpose
        dh = g_Blhi; dl = g_Bllo; dsti = i;
    }
    __nv_bfloat16 hi = __float2bfloat16(w);
    __nv_bfloat16 lo = __float2bfloat16(w - __bfloat162float(hi));
    dh[dsti] = hi;
    dl[dsti] = lo;
}

// ---------------- HMMA GEMM (BM=64, BN=128, split-bf16 3-term) ----------------
// FINAL=0: Y16[r] = fp16(X @ Wt[r]^T), fused sq/sk scores.
// FINAL=1: Yf = X @ Wl^T + bias (fp32, straight to d_out).
template <bool FINAL>
__global__ void __launch_bounds__(256)
k_gemm_tc(const float* __restrict__ X,
          const __nv_bfloat16* __restrict__ Bhi, const __nv_bfloat16* __restrict__ Blo,
          __half* __restrict__ Y16, float* __restrict__ Yf,
          float* __restrict__ sq, float* __restrict__ sk,
          const float* __restrict__ qv, const float* __restrict__ kv,
          const float* __restrict__ bias)
{
    extern __shared__ __align__(16) char dynsm[];
    char* sAhi = dynsm;
    char* sAlo = dynsm + ATILE;
    char* sBhi = dynsm + 2 * ATILE;
    char* sBlo = dynsm + 2 * ATILE + BTILE;

    __shared__ float s_q[128], s_k[128], s_b[128];
    __shared__ float s_redq[256], s_redk[256];

    const int tid  = threadIdx.x;
    const int wid  = tid >> 5;
    const int lane = tid & 31;
    const int mw   = wid & 1;          // m offset 32*mw
    const int nw   = wid >> 1;         // n offset 32*nw
    const int r    = blockIdx.y;
    const int row0 = blockIdx.x * 64;

    if (!FINAL) {
        if (tid < 128) { s_q[tid] = qv[tid]; s_k[tid] = kv[tid]; }
    } else {
        if (tid < 128) s_b[tid] = bias[tid];
    }

    // --- B copy gmem [N=128][K=128] -> smem padded rows (hi and lo) ---
    {
        const uint4* gh = (const uint4*)(Bhi + (size_t)r * 16384);
        const uint4* gl = (const uint4*)(Blo + (size_t)r * 16384);
#pragma unroll
        for (int i = 0; i < 8; i++) {
            int c = tid + 256 * i;             // 2048 16B-chunks
            int row = c >> 4, c16 = c & 15;
            uint32_t off = row * ROWB + c16 * 16;
            *(uint4*)(sBhi + off) = gh[c];
            *(uint4*)(sBlo + off) = gl[c];
        }
    }
    // --- A convert: fp32 -> bf16 hi/lo into padded rows (64 rows) ---
#pragma unroll
    for (int i = 0; i < 4; i++) {
        int c   = tid + 256 * i;               // 1024 chunks of 8 floats
        int row = c >> 4;
        int kc  = (c & 15) << 3;
        int grow = row0 + row;
        float v[8];
        if (grow < NN) {
            const float4* p = (const float4*)&X[(size_t)grow * 128 + kc];
            float4 f0 = p[0], f1 = p[1];
            v[0]=f0.x; v[1]=f0.y; v[2]=f0.z; v[3]=f0.w;
            v[4]=f1.x; v[5]=f1.y; v[6]=f1.z; v[7]=f1.w;
        } else {
#pragma unroll
            for (int j = 0; j < 8; j++) v[j] = 0.f;
        }
        uint32_t hp[4], lp[4];
#pragma unroll
        for (int j = 0; j < 4; j++) {
            __nv_bfloat16 h0 = __float2bfloat16(v[2*j]);
            __nv_bfloat16 h1 = __float2bfloat16(v[2*j+1]);
            __nv_bfloat16 l0 = __float2bfloat16(v[2*j]   - __bfloat162float(h0));
            __nv_bfloat16 l1 = __float2bfloat16(v[2*j+1] - __bfloat162float(h1));
            hp[j] = (uint32_t)__bfloat16_as_ushort(h0) | ((uint32_t)__bfloat16_as_ushort(h1) << 16);
            lp[j] = (uint32_t)__bfloat16_as_ushort(l0) | ((uint32_t)__bfloat16_as_ushort(l1) << 16);
        }
        uint32_t off = row * ROWB + kc * 2;
        *(uint4*)(sAhi + off) = make_uint4(hp[0], hp[1], hp[2], hp[3]);
        *(uint4*)(sAlo + off) = make_uint4(lp[0], lp[1], lp[2], lp[3]);
    }
    __syncthreads();

    // --- mainloop: c += Ahi*Bhi + Ahi*Blo + Alo*Bhi ---
    float acc[2][4][4];
#pragma unroll
    for (int mt = 0; mt < 2; mt++)
#pragma unroll
        for (int nt = 0; nt < 4; nt++)
#pragma unroll
            for (int j = 0; j < 4; j++) acc[mt][nt][j] = 0.f;

    const uint32_t aHiB = smem_u32(sAhi), aLoB = smem_u32(sAlo);
    const uint32_t bHiB = smem_u32(sBhi), bLoB = smem_u32(sBlo);
    const int arow  = mw * 32 + (lane & 7) + ((lane >> 3) & 1) * 8;
    const int akcol = (lane >> 4) * 8;
    const uint32_t aoff = (uint32_t)(arow * ROWB + akcol * 2);
    const int brow  = nw * 32 + (lane & 7) + ((lane >> 4) & 1) * 8;
    const int bkcol = ((lane >> 3) & 1) * 8;
    const uint32_t boff = (uint32_t)(brow * ROWB + bkcol * 2);

#pragma unroll
    for (int ks = 0; ks < 8; ks++) {
        const uint32_t ko = ks * 32;           // 16 k-cols * 2B
        uint32_t ah[2][4], al[2][4], bh[2][4], bl[2][4];
        ldsm4(ah[0], aHiB + aoff + ko);
        ldsm4(ah[1], aHiB + aoff + 16 * ROWB + ko);
        ldsm4(al[0], aLoB + aoff + ko);
        ldsm4(al[1], aLoB + aoff + 16 * ROWB + ko);
        ldsm4(bh[0], bHiB + boff + ko);
        ldsm4(bh[1], bHiB + boff + 16 * ROWB + ko);
        ldsm4(bl[0], bLoB + boff + ko);
        ldsm4(bl[1], bLoB + boff + 16 * ROWB + ko);
#pragma unroll
        for (int mt = 0; mt < 2; mt++)
#pragma unroll
            for (int p = 0; p < 2; p++) {
                mma16816(acc[mt][2*p],   ah[mt], bh[p][0], bh[p][1]);
                mma16816(acc[mt][2*p],   ah[mt], bl[p][0], bl[p][1]);
                mma16816(acc[mt][2*p],   al[mt], bh[p][0], bh[p][1]);
                mma16816(acc[mt][2*p+1], ah[mt], bh[p][2], bh[p][3]);
                mma16816(acc[mt][2*p+1], ah[mt], bl[p][2], bl[p][3]);
                mma16816(acc[mt][2*p+1], al[mt], bh[p][2], bh[p][3]);
            }
    }
    __syncthreads();    // everyone done reading sA/sB; reuse sAhi as staging

    if (!FINAL) {
        // --- scores + fp16 smem staging ---
        float pq[4] = {0.f, 0.f, 0.f, 0.f};
        float pk[4] = {0.f, 0.f, 0.f, 0.f};
#pragma unroll
        for (int mt = 0; mt < 2; mt++) {
            const int lrow = mw * 32 + mt * 16 + (lane >> 2);
#pragma unroll
            for (int nt = 0; nt < 4; nt++) {
                const int col = nw * 32 + nt * 8 + (lane & 3) * 2;
                float c0 = acc[mt][nt][0], c1 = acc[mt][nt][1];
                float c2 = acc[mt][nt][2], c3 = acc[mt][nt][3];
                float q0 = s_q[col], q1 = s_q[col + 1];
                float k0 = s_k[col], k1 = s_k[col + 1];
                pq[mt*2]   += c0 * q0 + c1 * q1;
                pq[mt*2+1] += c2 * q0 + c3 * q1;
                pk[mt*2]   += c0 * k0 + c1 * k1;
                pk[mt*2+1] += c2 * k0 + c3 * k1;
                *(__half2*)(sAhi + lrow * ROWB + col * 2)       = __floats2half2_rn(c0, c1);
                *(__half2*)(sAhi + (lrow + 8) * ROWB + col * 2) = __floats2half2_rn(c2, c3);
            }
        }
#pragma unroll
        for (int off = 1; off <= 2; off <<= 1)
#pragma unroll
            for (int j = 0; j < 4; j++) {
                pq[j] += __shfl_xor_sync(0xffffffffu, pq[j], off);
                pk[j] += __shfl_xor_sync(0xffffffffu, pk[j], off);
            }
        if ((lane & 3) == 0) {
#pragma unroll
            for (int mt = 0; mt < 2; mt++) {
                int lrow = mw * 32 + mt * 16 + (lane >> 2);
                s_redq[nw * 64 + lrow]     = pq[mt*2];
                s_redq[nw * 64 + lrow + 8] = pq[mt*2+1];
                s_redk[nw * 64 + lrow]     = pk[mt*2];
                s_redk[nw * 64 + lrow + 8] = pk[mt*2+1];
            }
        }
        __syncthreads();
        if (tid < 64) {
            int grow = row0 + tid;
            if (grow < NN) {
                sq[r * NN + grow] = s_redq[tid] + s_redq[64 + tid] + s_redq[128 + tid] + s_redq[192 + tid];
                sk[r * NN + grow] = s_redk[tid] + s_redk[64 + tid] + s_redk[128 + tid] + s_redk[192 + tid];
            }
        }
        // --- coalesced bulk copy: 64 rows x 128 halves ---
#pragma unroll
        for (int i = 0; i < 4; i++) {
            int c = tid + 256 * i;             // 1024 uint4
            int row = c >> 4, seg = c & 15;
            int grow = row0 + row;
            if (grow < NN)
                *(uint4*)&Y16[((size_t)r * NN + grow) * HH + seg * 8] =
                    *(const uint4*)(sAhi + row * ROWB + seg * 16);
        }
    } else {
        // --- fp32 staging with bias, then coalesced copy ---
#pragma unroll
        for (int mt = 0; mt < 2; mt++) {
            const int lrow = mw * 32 + mt * 16 + (lane >> 2);
#pragma unroll
            for (int nt = 0; nt < 4; nt++) {
                const int col = nw * 32 + nt * 8 + (lane & 3) * 2;
                float b0 = s_b[col], b1 = s_b[col + 1];
                *(float2*)(sAhi + lrow * F32STRIDE + col * 4) =
                    make_float2(acc[mt][nt][0] + b0, acc[mt][nt][1] + b1);
                *(float2*)(sAhi + (lrow + 8) * F32STRIDE + col * 4) =
                    make_float2(acc[mt][nt][2] + b0, acc[mt][nt][3] + b1);
            }
        }
        __syncthreads();
#pragma unroll
        for (int i = 0; i < 8; i++) {
            int c = tid + 256 * i;             // 2048 uint4
            int row = c >> 5, seg = c & 31;
            int grow = row0 + row;
            if (grow < NN)
                *(uint4*)&Yf[(size_t)grow * HH + seg * 4] =
                    *(const uint4*)(sAhi + row * F32STRIDE + seg * 16);
        }
    }
}

// ---------------- single-pass softmax + aggregation (warp per node) -----------
__global__ void __launch_bounds__(256)
k_agg(const __half* __restrict__ xW, const float* __restrict__ sq,
      const float* __restrict__ sk, const float* __restrict__ bias,
      float* __restrict__ out)
{
    int warp = (blockIdx.x * blockDim.x + threadIdx.x) >> 5;
    int lane = threadIdx.x & 31;
    if (warp >= NN) return;
    const int n     = warp;
    const int start = g_rowptr[n];
    const int end   = g_rowptr[n + 1];

    // sq has only R=8 distinct values for this node: keep in registers
    float sqv = (lane < RR) ? sq[lane * NN + n] : 0.f;

    float4 acc = make_float4(0.f, 0.f, 0.f, 0.f);
    float den = 0.f;
    for (int j0 = start; j0 < end; j0 += 32) {
        int j = j0 + lane;
        int p = (j < end) ? g_edges[j] : 0;
        int s = p & 0xffff, et = p >> 16;
        float v = __shfl_sync(0xffffffffu, sqv, et) + sk[et * NN + s];
        v = v > 0.f ? v : NEG * v;
        float w = (j < end) ? __expf(v) : 0.f;     // no max-subtract: shift-invariant
        den += w;
        int cnt = min(32, end - j0);
        for (int t = 0; t < cnt; t++) {
            float wt = __shfl_sync(0xffffffffu, w, t);
            int   pt = __shfl_sync(0xffffffffu, p, t);
            int st = pt & 0xffff, rt = pt >> 16;
            const uint2 raw = *(const uint2*)&xW[((size_t)rt * NN + st) * HH + lane * 4];
            __half2 h01 = *(const __half2*)&raw.x;
            __half2 h23 = *(const __half2*)&raw.y;
            float2 f01 = __half22float2(h01);
            float2 f23 = __half22float2(h23);
            acc.x += wt * f01.x;
            acc.y += wt * f01.y;
            acc.z += wt * f23.x;
            acc.w += wt * f23.y;
        }
    }
#pragma unroll
    for (int off = 16; off; off >>= 1)
        den += __shfl_xor_sync(0xffffffffu, den, off);

    float inv = 1.f / (den + 1e-16f);
    float4 bv = *(const float4*)&bias[lane * 4];
    float4 o;
    o.x = fmaxf(acc.x * inv + bv.x, 0.f);
    o.y = fmaxf(acc.y * inv + bv.y, 0.f);
    o.z = fmaxf(acc.z * inv + bv.z, 0.f);
    o.w = fmaxf(acc.w * inv + bv.w, 0.f);
    *(float4*)&out[(size_t)n * HH + lane * 4] = o;
}

// ---------------- launch ------------------------------------------------------
extern "C" void kernel_launch(void* const* d_in, const int* in_sizes, int n_in,
                              void* d_out, int out_size)
{
    const float* x  = (const float*)d_in[0];
    const int*   ei = (const int*)  d_in[1];
    const int*   et = (const int*)  d_in[2];
    const float* W1 = (const float*)d_in[4];
    const float* q1 = (const float*)d_in[5];
    const float* k1 = (const float*)d_in[6];
    const float* b1 = (const float*)d_in[7];
    const float* W2 = (const float*)d_in[8];
    const float* q2 = (const float*)d_in[9];
    const float* k2 = (const float*)d_in[10];
    const float* b2 = (const float*)d_in[11];
    const float* Wl = (const float*)d_in[12];
    const float* bl = (const float*)d_in[13];
    float* out = (float*)d_out;

    const int* srcp = ei;
    const int* tgtp = ei + EE;

    float *ph, *psq, *psk;
    __half* pxW;
    __nv_bfloat16 *pB1h, *pB1l, *pB2h, *pB2l, *pBlh, *pBll;
    cudaGetSymbolAddress((void**)&pxW, g_xW16);
    cudaGetSymbolAddress((void**)&ph,  g_h);
    cudaGetSymbolAddress((void**)&psq, g_sq);
    cudaGetSymbolAddress((void**)&psk, g_sk);
    cudaGetSymbolAddress((void**)&pB1h, g_B1hi);
    cudaGetSymbolAddress((void**)&pB1l, g_B1lo);
    cudaGetSymbolAddress((void**)&pB2h, g_B2hi);
    cudaGetSymbolAddress((void**)&pB2l, g_B2lo);
    cudaGetSymbolAddress((void**)&pBlh, g_Blhi);
    cudaGetSymbolAddress((void**)&pBll, g_Bllo);

    cudaFuncSetAttribute(k_gemm_tc<false>, cudaFuncAttributeMaxDynamicSharedMemorySize, SMEM_TC);
    cudaFuncSetAttribute(k_gemm_tc<true>,  cudaFuncAttributeMaxDynamicSharedMemorySize, SMEM_TC);

    // CSR build + weight prep
    k_zero_deg<<<(NN + 255) / 256, 256>>>();
    k_hist<<<(EE + 255) / 256, 256>>>(tgtp);
    k_scan_one<<<1, SCAN_T>>>();
    k_fill<<<(EE + 255) / 256, 256>>>(srcp, tgtp, et);
    k_prep<<<((2 * RR + 1) * 16384 + 255) / 256, 256>>>(W1, W2, Wl);

    const int GT64 = (NN + 63) / 64;           // 782 row tiles
    dim3 tc_grid(GT64, RR);
    const int agg_blocks = (NN * 32 + 255) / 256;

    // Layer 1
    k_gemm_tc<false><<<tc_grid, 256, SMEM_TC>>>(x,  pB1h, pB1l, pxW, nullptr,
                                                psq, psk, q1, k1, nullptr);
    k_agg<<<agg_blocks, 256>>>(pxW, psq, psk, b1, ph);

    // Layer 2
    k_gemm_tc<false><<<tc_grid, 256, SMEM_TC>>>(ph, pB2h, pB2l, pxW, nullptr,
                                                psq, psk, q2, k2, nullptr);
    k_agg<<<agg_blocks, 256>>>(pxW, psq, psk, b2, ph);

    // Final linear (h @ Wl^T + bl) straight into d_out
    k_gemm_tc<true><<<dim3(GT64, 1), 256, SMEM_TC>>>(ph, pBlh, pBll, nullptr, out,
                                                     nullptr, nullptr, nullptr, nullptr, bl);
    (void)in_sizes; (void)n_in; (void)out_size;
}

// round 6
// speedup vs baseline: 1.8789x; 1.0884x over previous
#include <cuda_runtime.h>
#include <cuda_bf16.h>
#include <cuda_fp16.h>
#include <cstdint>

#define NN   50000
#define EE   800000
#define RR   8
#define HH   128
#define NEG  0.2f
#define SCAN_T 1024

// ---------------- scratch (device globals; no runtime allocation) -------------
__device__ __half g_xW16[RR * NN * HH];    // [R,N,H] per-relation transforms (fp16)
__device__ float g_sq[RR * NN];            // xW . q (fp32)
__device__ float g_sk[RR * NN];            // xW . k
__device__ int   g_rowptr[NN + 1];
__device__ int   g_cursor[NN];
__device__ int   g_edges [EE];             // packed: src | (etype<<16)
// pre-split bf16 hi/lo activation images
__device__ __nv_bfloat16 g_Xhi[NN * HH];
__device__ __nv_bfloat16 g_Xlo[NN * HH];
__device__ __nv_bfloat16 g_Hhi[NN * HH];   // layer outputs (reused l1 -> l2)
__device__ __nv_bfloat16 g_Hlo[NN * HH];
// bf16 hi/lo weight images, [R][N][K] plain layout
__device__ __nv_bfloat16 g_B1hi[RR * 16384];
__device__ __nv_bfloat16 g_B1lo[RR * 16384];
__device__ __nv_bfloat16 g_B2hi[RR * 16384];
__device__ __nv_bfloat16 g_B2lo[RR * 16384];
__device__ __nv_bfloat16 g_Blhi[16384];    // final linear (Wl, no transpose)
__device__ __nv_bfloat16 g_Bllo[16384];

// ---------------- PTX helpers -------------------------------------------------
__device__ __forceinline__ uint32_t smem_u32(const void* p) {
    uint32_t a;
    asm("{ .reg .u64 t; cvta.to.shared.u64 t, %1; cvt.u32.u64 %0, t; }" : "=r"(a) : "l"(p));
    return a;
}
__device__ __forceinline__ void ldsm4(uint32_t* r, uint32_t addr) {
    asm volatile("ldmatrix.sync.aligned.m8n8.x4.shared.b16 {%0,%1,%2,%3}, [%4];"
                 : "=r"(r[0]), "=r"(r[1]), "=r"(r[2]), "=r"(r[3]) : "r"(addr));
}
__device__ __forceinline__ void mma16816(float* c, const uint32_t* a,
                                         uint32_t b0, uint32_t b1) {
    asm volatile(
        "mma.sync.aligned.m16n8k16.row.col.f32.bf16.bf16.f32 "
        "{%0,%1,%2,%3}, {%4,%5,%6,%7}, {%8,%9}, {%0,%1,%2,%3};"
        : "+f"(c[0]), "+f"(c[1]), "+f"(c[2]), "+f"(c[3])
        : "r"(a[0]), "r"(a[1]), "r"(a[2]), "r"(a[3]), "r"(b0), "r"(b1));
}
__device__ __forceinline__ void split_bf16(float v, __nv_bfloat16& hi, __nv_bfloat16& lo) {
    hi = __float2bfloat16(v);
    lo = __float2bfloat16(v - __bfloat162float(hi));
}

// smem geometry
#define ROWB 272                      // padded bf16 row: 136 halves = 272 B
#define ATILE (64 * ROWB)             // 17408
#define BTILE (128 * ROWB)            // 34816
#define SMEM_TC (2 * ATILE + 2 * BTILE)   // 104448
#define F32STRIDE 528                 // fp32 epilogue staging row stride (bytes)

// ---------------- activation pre-split: fp32 -> bf16 hi/lo --------------------
__global__ void k_convX(const float* __restrict__ X,
                        __nv_bfloat16* __restrict__ Xhi, __nv_bfloat16* __restrict__ Xlo) {
    int c = blockIdx.x * blockDim.x + threadIdx.x;     // 800000 chunks of 8
    if (c >= NN * 16) return;
    const float4* p = (const float4*)(X + (size_t)c * 8);
    float4 f0 = p[0], f1 = p[1];
    float v[8] = {f0.x, f0.y, f0.z, f0.w, f1.x, f1.y, f1.z, f1.w};
    uint32_t hw[4], lw[4];
#pragma unroll
    for (int j = 0; j < 4; j++) {
        __nv_bfloat16 h0, l0, h1, l1;
        split_bf16(v[2*j], h0, l0);
        split_bf16(v[2*j+1], h1, l1);
        hw[j] = (uint32_t)__bfloat16_as_ushort(h0) | ((uint32_t)__bfloat16_as_ushort(h1) << 16);
        lw[j] = (uint32_t)__bfloat16_as_ushort(l0) | ((uint32_t)__bfloat16_as_ushort(l1) << 16);
    }
    *(uint4*)(Xhi + (size_t)c * 8) = make_uint4(hw[0], hw[1], hw[2], hw[3]);
    *(uint4*)(Xlo + (size_t)c * 8) = make_uint4(lw[0], lw[1], lw[2], lw[3]);
}

// ---------------- weight prep: all weights -> bf16 hi/lo images ---------------
__global__ void k_prep(const float* __restrict__ W1, const float* __restrict__ W2,
                       const float* __restrict__ Wl) {
    int idx = blockIdx.x * blockDim.x + threadIdx.x;
    const int RW = RR * 16384;
    if (idx >= 2 * RW + 16384) return;
    float w;
    __nv_bfloat16 *dh, *dl;
    int dsti;
    if (idx < 2 * RW) {
        const float* W = (idx < RW) ? W1 : W2;
        int i = (idx < RW) ? idx : idx - RW;
        int r = i >> 14, rem = i & 16383;
        int n = rem >> 7, k = rem & 127;
        w = W[r * 16384 + k * 128 + n];          // transpose: Wt[n][k] = W[k][n]
        dh = (idx < RW) ? g_B1hi : g_B2hi;
        dl = (idx < RW) ? g_B1lo : g_B2lo;
        dsti = r * 16384 + n * 128 + k;
    } else {
        int i = idx - 2 * RW;
        w = Wl[i];                               // B[j][k] = Wl[j][k], no transpose
        dh = g_Blhi; dl = g_Bllo; dsti = i;
    }
    __nv_bfloat16 hi, lo;
    split_bf16(w, hi, lo);
    dh[dsti] = hi;
    dl[dsti] = lo;
}

// ---------------- CSR build ---------------------------------------------------
__global__ void k_zero_deg() {
    int i = blockIdx.x * blockDim.x + threadIdx.x;
    if (i < NN) g_cursor[i] = 0;
}
__global__ void k_hist(const int* __restrict__ tgt) {
    int e = blockIdx.x * blockDim.x + threadIdx.x;
    if (e < EE) atomicAdd(&g_cursor[tgt[e]], 1);
}
__global__ void __launch_bounds__(SCAN_T) k_scan_one() {
    __shared__ int part[SCAN_T];
    int t = threadIdx.x;
    const int per = (NN + SCAN_T - 1) / SCAN_T;
    int lo = t * per;
    int hi = lo + per; if (hi > NN) hi = NN;
    int s = 0;
    for (int i = lo; i < hi; i++) s += g_cursor[i];
    part[t] = s;
    __syncthreads();
    for (int off = 1; off < SCAN_T; off <<= 1) {
        int v = (t >= off) ? part[t - off] : 0;
        __syncthreads();
        part[t] += v;
        __syncthreads();
    }
    int run = (t > 0) ? part[t - 1] : 0;
    for (int i = lo; i < hi; i++) {
        int d = g_cursor[i];
        g_rowptr[i] = run;
        g_cursor[i] = run;
        run += d;
    }
    if (t == 0) g_rowptr[NN] = EE;
}
__global__ void k_fill(const int* __restrict__ src, const int* __restrict__ tgt,
                       const int* __restrict__ etype) {
    int e = blockIdx.x * blockDim.x + threadIdx.x;
    if (e < EE) {
        int t = tgt[e];
        int pos = atomicAdd(&g_cursor[t], 1);
        g_edges[pos] = src[e] | (etype[e] << 16);
    }
}

// ---------------- HMMA GEMM (2 row-tiles of 64 per block, BN=128) -------------
// FINAL=0: Y16[r] = fp16(A @ B[r]^T), fused sq/sk scores.
// FINAL=1: Yf = A @ Wl^T + bias (fp32, straight to d_out).
template <bool FINAL>
__global__ void __launch_bounds__(256)
k_gemm_tc(const __nv_bfloat16* __restrict__ Ahig, const __nv_bfloat16* __restrict__ Alog,
          const __nv_bfloat16* __restrict__ Bhi, const __nv_bfloat16* __restrict__ Blo,
          __half* __restrict__ Y16, float* __restrict__ Yf,
          float* __restrict__ sq, float* __restrict__ sk,
          const float* __restrict__ qv, const float* __restrict__ kv,
          const float* __restrict__ bias)
{
    extern __shared__ __align__(16) char dynsm[];
    char* sAhi = dynsm;
    char* sAlo = dynsm + ATILE;
    char* sBhi = dynsm + 2 * ATILE;
    char* sBlo = dynsm + 2 * ATILE + BTILE;

    __shared__ float s_q[128], s_k[128], s_b[128];
    __shared__ float s_redq[256], s_redk[256];

    const int tid  = threadIdx.x;
    const int wid  = tid >> 5;
    const int lane = tid & 31;
    const int mw   = wid & 1;
    const int nw   = wid >> 1;
    const int r    = blockIdx.y;
    const int base = blockIdx.x * 128;

    if (!FINAL) {
        if (tid < 128) { s_q[tid] = qv[tid]; s_k[tid] = kv[tid]; }
    } else {
        if (tid < 128) s_b[tid] = bias[tid];
    }

    // --- B copy gmem [N=128][K=128] -> smem padded rows (hi and lo) ---
    {
        const uint4* gh = (const uint4*)(Bhi + (size_t)r * 16384);
        const uint4* gl = (const uint4*)(Blo + (size_t)r * 16384);
#pragma unroll
        for (int i = 0; i < 8; i++) {
            int c = tid + 256 * i;
            int row = c >> 4, c16 = c & 15;
            uint32_t off = row * ROWB + c16 * 16;
            *(uint4*)(sBhi + off) = gh[c];
            *(uint4*)(sBlo + off) = gl[c];
        }
    }

    const uint32_t aHiB = smem_u32(sAhi), aLoB = smem_u32(sAlo);
    const uint32_t bHiB = smem_u32(sBhi), bLoB = smem_u32(sBlo);
    const int arow  = mw * 32 + (lane & 7) + ((lane >> 3) & 1) * 8;
    const int akcol = (lane >> 4) * 8;
    const uint32_t aoff = (uint32_t)(arow * ROWB + akcol * 2);
    const int brow  = nw * 32 + (lane & 7) + ((lane >> 4) & 1) * 8;
    const int bkcol = ((lane >> 3) & 1) * 8;
    const uint32_t boff = (uint32_t)(brow * ROWB + bkcol * 2);

    for (int tile = 0; tile < 2; tile++) {
        const int row0 = base + tile * 64;

        // --- A copy: pre-split bf16 rows -> smem padded (64 rows) ---
#pragma unroll
        for (int i = 0; i < 4; i++) {
            int c = tid + 256 * i;               // 1024 chunks of 8 halves
            int row = c >> 4, seg = c & 15;
            int grow = row0 + row;
            uint4 vh = make_uint4(0, 0, 0, 0), vl = make_uint4(0, 0, 0, 0);
            if (grow < NN) {
                vh = *(const uint4*)(Ahig + (size_t)grow * HH + seg * 8);
                vl = *(const uint4*)(Alog + (size_t)grow * HH + seg * 8);
            }
            uint32_t off = row * ROWB + seg * 16;
            *(uint4*)(sAhi + off) = vh;
            *(uint4*)(sAlo + off) = vl;
        }
        __syncthreads();

        // --- mainloop: c += Ahi*Bhi + Ahi*Blo + Alo*Bhi ---
        float acc[2][4][4];
#pragma unroll
        for (int mt = 0; mt < 2; mt++)
#pragma unroll
            for (int nt = 0; nt < 4; nt++)
#pragma unroll
                for (int j = 0; j < 4; j++) acc[mt][nt][j] = 0.f;

#pragma unroll
        for (int ks = 0; ks < 8; ks++) {
            const uint32_t ko = ks * 32;
            uint32_t ah[2][4], al[2][4], bh[2][4], bl[2][4];
            ldsm4(ah[0], aHiB + aoff + ko);
            ldsm4(ah[1], aHiB + aoff + 16 * ROWB + ko);
            ldsm4(al[0], aLoB + aoff + ko);
            ldsm4(al[1], aLoB + aoff + 16 * ROWB + ko);
            ldsm4(bh[0], bHiB + boff + ko);
            ldsm4(bh[1], bHiB + boff + 16 * ROWB + ko);
            ldsm4(bl[0], bLoB + boff + ko);
            ldsm4(bl[1], bLoB + boff + 16 * ROWB + ko);
#pragma unroll
            for (int mt = 0; mt < 2; mt++)
#pragma unroll
                for (int p = 0; p < 2; p++) {
                    mma16816(acc[mt][2*p],   ah[mt], bh[p][0], bh[p][1]);
                    mma16816(acc[mt][2*p],   ah[mt], bl[p][0], bl[p][1]);
                    mma16816(acc[mt][2*p],   al[mt], bh[p][0], bh[p][1]);
                    mma16816(acc[mt][2*p+1], ah[mt], bh[p][2], bh[p][3]);
                    mma16816(acc[mt][2*p+1], ah[mt], bl[p][2], bl[p][3]);
                    mma16816(acc[mt][2*p+1], al[mt], bh[p][2], bh[p][3]);
                }
        }
        __syncthreads();    // done reading sA; reuse sAhi(+sAlo) as staging

        if (!FINAL) {
            float pq[4] = {0.f, 0.f, 0.f, 0.f};
            float pk[4] = {0.f, 0.f, 0.f, 0.f};
#pragma unroll
            for (int mt = 0; mt < 2; mt++) {
                const int lrow = mw * 32 + mt * 16 + (lane >> 2);
#pragma unroll
                for (int nt = 0; nt < 4; nt++) {
                    const int col = nw * 32 + nt * 8 + (lane & 3) * 2;
                    float c0 = acc[mt][nt][0], c1 = acc[mt][nt][1];
                    float c2 = acc[mt][nt][2], c3 = acc[mt][nt][3];
                    float q0 = s_q[col], q1 = s_q[col + 1];
                    float k0 = s_k[col], k1 = s_k[col + 1];
                    pq[mt*2]   += c0 * q0 + c1 * q1;
                    pq[mt*2+1] += c2 * q0 + c3 * q1;
                    pk[mt*2]   += c0 * k0 + c1 * k1;
                    pk[mt*2+1] += c2 * k0 + c3 * k1;
                    *(__half2*)(sAhi + lrow * ROWB + col * 2)       = __floats2half2_rn(c0, c1);
                    *(__half2*)(sAhi + (lrow + 8) * ROWB + col * 2) = __floats2half2_rn(c2, c3);
                }
            }
#pragma unroll
            for (int off = 1; off <= 2; off <<= 1)
#pragma unroll
                for (int j = 0; j < 4; j++) {
                    pq[j] += __shfl_xor_sync(0xffffffffu, pq[j], off);
                    pk[j] += __shfl_xor_sync(0xffffffffu, pk[j], off);
                }
            if ((lane & 3) == 0) {
#pragma unroll
                for (int mt = 0; mt < 2; mt++) {
                    int lrow = mw * 32 + mt * 16 + (lane >> 2);
                    s_redq[nw * 64 + lrow]     = pq[mt*2];
                    s_redq[nw * 64 + lrow + 8] = pq[mt*2+1];
                    s_redk[nw * 64 + lrow]     = pk[mt*2];
                    s_redk[nw * 64 + lrow + 8] = pk[mt*2+1];
                }
            }
            __syncthreads();
            if (tid < 64) {
                int grow = row0 + tid;
                if (grow < NN) {
                    sq[r * NN + grow] = s_redq[tid] + s_redq[64 + tid] + s_redq[128 + tid] + s_redq[192 + tid];
                    sk[r * NN + grow] = s_redk[tid] + s_redk[64 + tid] + s_redk[128 + tid] + s_redk[192 + tid];
                }
            }
#pragma unroll
            for (int i = 0; i < 4; i++) {
                int c = tid + 256 * i;
                int row = c >> 4, seg = c & 15;
                int grow = row0 + row;
                if (grow < NN)
                    *(uint4*)&Y16[((size_t)r * NN + grow) * HH + seg * 8] =
                        *(const uint4*)(sAhi + row * ROWB + seg * 16);
            }
        } else {
#pragma unroll
            for (int mt = 0; mt < 2; mt++) {
                const int lrow = mw * 32 + mt * 16 + (lane >> 2);
#pragma unroll
                for (int nt = 0; nt < 4; nt++) {
                    const int col = nw * 32 + nt * 8 + (lane & 3) * 2;
                    float b0 = s_b[col], b1 = s_b[col + 1];
                    *(float2*)(sAhi + lrow * F32STRIDE + col * 4) =
                        make_float2(acc[mt][nt][0] + b0, acc[mt][nt][1] + b1);
                    *(float2*)(sAhi + (lrow + 8) * F32STRIDE + col * 4) =
                        make_float2(acc[mt][nt][2] + b0, acc[mt][nt][3] + b1);
                }
            }
            __syncthreads();
#pragma unroll
            for (int i = 0; i < 8; i++) {
                int c = tid + 256 * i;
                int row = c >> 5, seg = c & 31;
                int grow = row0 + row;
                if (grow < NN)
                    *(uint4*)&Yf[(size_t)grow * HH + seg * 4] =
                        *(const uint4*)(sAhi + row * F32STRIDE + seg * 16);
            }
        }
        __syncthreads();    // staging free before next tile's A copy
    }
}

// ---------------- single-pass softmax + aggregation (warp per node) -----------
// 2 edges per inner iteration: 16 lanes x 16B cover each 256B row.
// Output: bf16 hi/lo split of relu(agg + bias) for the next GEMM.
__global__ void __launch_bounds__(256)
k_agg(const __half* __restrict__ xW, const float* __restrict__ sq,
      const float* __restrict__ sk, const float* __restrict__ bias,
      __nv_bfloat16* __restrict__ outHi, __nv_bfloat16* __restrict__ outLo)
{
    int warp = (blockIdx.x * blockDim.x + threadIdx.x) >> 5;
    int lane = threadIdx.x & 31;
    if (warp >= NN) return;
    const int n     = warp;
    const int start = g_rowptr[n];
    const int end   = g_rowptr[n + 1];

    float sqv = (lane < RR) ? sq[lane * NN + n] : 0.f;

    const int half16 = lane >> 4;           // which edge of the pair
    const int c8     = (lane & 15) * 8;     // 8-half column group

    float acc[8] = {0.f, 0.f, 0.f, 0.f, 0.f, 0.f, 0.f, 0.f};
    float den = 0.f;
    for (int j0 = start; j0 < end; j0 += 32) {
        int j = j0 + lane;
        int p = (j < end) ? g_edges[j] : 0;
        int s = p & 0xffff, et = p >> 16;
        float v = __shfl_sync(0xffffffffu, sqv, et) + sk[et * NN + s];
        v = v > 0.f ? v : NEG * v;
        float w = (j < end) ? __expf(v) : 0.f;
        den += w;
        int cnt = min(32, end - j0);
        for (int t = 0; t < cnt; t += 2) {
            int idx  = t + half16;
            int idxc = (idx < cnt) ? idx : cnt - 1;
            float wt = __shfl_sync(0xffffffffu, w, idxc);
            int   pt = __shfl_sync(0xffffffffu, p, idxc);
            if (idx >= cnt) wt = 0.f;
            int st = pt & 0xffff, rt = pt >> 16;
            uint4 raw = *(const uint4*)&xW[((size_t)rt * NN + st) * HH + c8];
            const __half2* hp = (const __half2*)&raw;
#pragma unroll
            for (int k = 0; k < 4; k++) {
                float2 f = __half22float2(hp[k]);
                acc[2*k]   += wt * f.x;
                acc[2*k+1] += wt * f.y;
            }
        }
    }
#pragma unroll
    for (int j = 0; j < 8; j++)
        acc[j] += __shfl_xor_sync(0xffffffffu, acc[j], 16);
#pragma unroll
    for (int off = 16; off; off >>= 1)
        den += __shfl_xor_sync(0xffffffffu, den, off);

    if (lane < 16) {
        float inv = 1.f / (den + 1e-16f);
        float4 b0 = *(const float4*)&bias[lane * 8];
        float4 b1 = *(const float4*)&bias[lane * 8 + 4];
        float o[8];
        o[0] = fmaxf(acc[0] * inv + b0.x, 0.f);
        o[1] = fmaxf(acc[1] * inv + b0.y, 0.f);
        o[2] = fmaxf(acc[2] * inv + b0.z, 0.f);
        o[3] = fmaxf(acc[3] * inv + b0.w, 0.f);
        o[4] = fmaxf(acc[4] * inv + b1.x, 0.f);
        o[5] = fmaxf(acc[5] * inv + b1.y, 0.f);
        o[6] = fmaxf(acc[6] * inv + b1.z, 0.f);
        o[7] = fmaxf(acc[7] * inv + b1.w, 0.f);
        uint32_t hw[4], lw[4];
#pragma unroll
        for (int j = 0; j < 4; j++) {
            __nv_bfloat16 h0, l0, h1, l1;
            split_bf16(o[2*j], h0, l0);
            split_bf16(o[2*j+1], h1, l1);
            hw[j] = (uint32_t)__bfloat16_as_ushort(h0) | ((uint32_t)__bfloat16_as_ushort(h1) << 16);
            lw[j] = (uint32_t)__bfloat16_as_ushort(l0) | ((uint32_t)__bfloat16_as_ushort(l1) << 16);
        }
        *(uint4*)&outHi[(size_t)n * HH + lane * 8] = make_uint4(hw[0], hw[1], hw[2], hw[3]);
        *(uint4*)&outLo[(size_t)n * HH + lane * 8] = make_uint4(lw[0], lw[1], lw[2], lw[3]);
    }
}

// ---------------- launch ------------------------------------------------------
extern "C" void kernel_launch(void* const* d_in, const int* in_sizes, int n_in,
                              void* d_out, int out_size)
{
    const float* x  = (const float*)d_in[0];
    const int*   ei = (const int*)  d_in[1];
    const int*   et = (const int*)  d_in[2];
    const float* W1 = (const float*)d_in[4];
    const float* q1 = (const float*)d_in[5];
    const float* k1 = (const float*)d_in[6];
    const float* b1 = (const float*)d_in[7];
    const float* W2 = (const float*)d_in[8];
    const float* q2 = (const float*)d_in[9];
    const float* k2 = (const float*)d_in[10];
    const float* b2 = (const float*)d_in[11];
    const float* Wl = (const float*)d_in[12];
    const float* bl = (const float*)d_in[13];
    float* out = (float*)d_out;

    const int* srcp = ei;
    const int* tgtp = ei + EE;

    float *psq, *psk;
    __half* pxW;
    __nv_bfloat16 *pXh, *pXl, *pHh, *pHl;
    __nv_bfloat16 *pB1h, *pB1l, *pB2h, *pB2l, *pBlh, *pBll;
    cudaGetSymbolAddress((void**)&pxW, g_xW16);
    cudaGetSymbolAddress((void**)&psq, g_sq);
    cudaGetSymbolAddress((void**)&psk, g_sk);
    cudaGetSymbolAddress((void**)&pXh, g_Xhi);
    cudaGetSymbolAddress((void**)&pXl, g_Xlo);
    cudaGetSymbolAddress((void**)&pHh, g_Hhi);
    cudaGetSymbolAddress((void**)&pHl, g_Hlo);
    cudaGetSymbolAddress((void**)&pB1h, g_B1hi);
    cudaGetSymbolAddress((void**)&pB1l, g_B1lo);
    cudaGetSymbolAddress((void**)&pB2h, g_B2hi);
    cudaGetSymbolAddress((void**)&pB2l, g_B2lo);
    cudaGetSymbolAddress((void**)&pBlh, g_Blhi);
    cudaGetSymbolAddress((void**)&pBll, g_Bllo);

    cudaFuncSetAttribute(k_gemm_tc<false>, cudaFuncAttributeMaxDynamicSharedMemorySize, SMEM_TC);
    cudaFuncSetAttribute(k_gemm_tc<true>,  cudaFuncAttributeMaxDynamicSharedMemorySize, SMEM_TC);

    const int GT128 = (NN + 127) / 128;        // 391
    dim3 tc_grid(GT128, RR);
    const int agg_blocks = (NN * 32 + 255) / 256;

    // Launch order chosen so k_gemm_tc (layer 1) is the 4th launch -> ncu capture.
    k_convX<<<(NN * 16 + 255) / 256, 256>>>(x, pXh, pXl);
    k_prep<<<((2 * RR + 1) * 16384 + 255) / 256, 256>>>(W1, W2, Wl);
    k_zero_deg<<<(NN + 255) / 256, 256>>>();
    k_gemm_tc<false><<<tc_grid, 256, SMEM_TC>>>(pXh, pXl, pB1h, pB1l, pxW, nullptr,
                                                psq, psk, q1, k1, nullptr);   // 4th
    k_hist<<<(EE + 255) / 256, 256>>>(tgtp);
    k_scan_one<<<1, SCAN_T>>>();
    k_fill<<<(EE + 255) / 256, 256>>>(srcp, tgtp, et);

    k_agg<<<agg_blocks, 256>>>(pxW, psq, psk, b1, pHh, pHl);

    k_gemm_tc<false><<<tc_grid, 256, SMEM_TC>>>(pHh, pHl, pB2h, pB2l, pxW, nullptr,
                                                psq, psk, q2, k2, nullptr);
    k_agg<<<agg_blocks, 256>>>(pxW, psq, psk, b2, pHh, pHl);

    k_gemm_tc<true><<<dim3(GT128, 1), 256, SMEM_TC>>>(pHh, pHl, pBlh, pBll, nullptr, out,
                                                      nullptr, nullptr, nullptr, nullptr, bl);
    (void)in_sizes; (void)n_in; (void)out_size;
}